// round 4
// baseline (speedup 1.0000x reference)
#include <cuda_runtime.h>
#include <cuda_bf16.h>
#include <math.h>
#include <stdint.h>

// Problem constants
#define HDIM   2880
#define NHEADS 64
#define NKV    8
#define DHEAD  64
#define GRP    8          // NHEADS / NKV
#define WIN    128
#define QKVW   5120       // (NHEADS + 2*NKV) * DHEAD
#define AOW    4096       // NHEADS * DHEAD
#define NMAX   1024
#define WO_NPAD 2944      // 23 * 128 (padded N for GEMM2)

// Scratch (device globals: allocation-free)
__device__ float g_qkv[NMAX * QKVW];   // 20 MB
__device__ int   g_positions[NMAX];

__device__ __align__(16) __nv_bfloat16 g_ahi[NMAX * HDIM];
__device__ __align__(16) __nv_bfloat16 g_alo[NMAX * HDIM];
__device__ __align__(16) __nv_bfloat16 g_athi[NMAX * AOW];
__device__ __align__(16) __nv_bfloat16 g_atlo[NMAX * AOW];
__device__ __align__(16) __nv_bfloat16 g_wqh[HDIM * QKVW];
__device__ __align__(16) __nv_bfloat16 g_wql[HDIM * QKVW];
__device__ __align__(16) __nv_bfloat16 g_woh[AOW * WO_NPAD];
__device__ __align__(16) __nv_bfloat16 g_wol[AOW * WO_NPAD];

// ---------------------------------------------------------------------------
// positions normalizer (int32 vs int64 robust; positions are arange here)
// ---------------------------------------------------------------------------
__global__ void norm_pos_kernel(const void* __restrict__ pos_raw, int n)
{
    const long long* p64 = (const long long*)pos_raw;
    const int*       p32 = (const int*)pos_raw;
    __shared__ int is64;
    if (threadIdx.x == 0) {
        long long v0 = p64[0];
        long long v1 = (n > 1) ? p64[1] : 1;
        is64 = (v0 == 0 && v1 == 1) ? 1 : 0;
    }
    __syncthreads();
    for (int i = threadIdx.x; i < n; i += blockDim.x)
        g_positions[i] = is64 ? (int)p64[i] : p32[i];
}

// ---------------------------------------------------------------------------
// fp32 -> bf16 hi/lo split (vectorized x4)
// ---------------------------------------------------------------------------
__device__ __forceinline__ void split4(float4 v, uint2& hv, uint2& lv)
{
    __nv_bfloat16 h0 = __float2bfloat16(v.x);
    __nv_bfloat16 h1 = __float2bfloat16(v.y);
    __nv_bfloat16 h2 = __float2bfloat16(v.z);
    __nv_bfloat16 h3 = __float2bfloat16(v.w);
    __nv_bfloat16 l0 = __float2bfloat16(v.x - __bfloat162float(h0));
    __nv_bfloat16 l1 = __float2bfloat16(v.y - __bfloat162float(h1));
    __nv_bfloat16 l2 = __float2bfloat16(v.z - __bfloat162float(h2));
    __nv_bfloat16 l3 = __float2bfloat16(v.w - __bfloat162float(h3));
    __nv_bfloat162 hp0 = __nv_bfloat162(h0, h1);
    __nv_bfloat162 hp1 = __nv_bfloat162(h2, h3);
    __nv_bfloat162 lp0 = __nv_bfloat162(l0, l1);
    __nv_bfloat162 lp1 = __nv_bfloat162(l2, l3);
    hv.x = *(uint32_t*)&hp0; hv.y = *(uint32_t*)&hp1;
    lv.x = *(uint32_t*)&lp0; lv.y = *(uint32_t*)&lp1;
}

__global__ void split_kernel(const float* __restrict__ src,
                             __nv_bfloat16* __restrict__ hi,
                             __nv_bfloat16* __restrict__ lo, int n4)
{
    int i = blockIdx.x * blockDim.x + threadIdx.x;
    if (i >= n4) return;
    float4 v = ((const float4*)src)[i];
    uint2 hv, lv;
    split4(v, hv, lv);
    ((uint2*)hi)[i] = hv;
    ((uint2*)lo)[i] = lv;
}

// padded split: src is rows x ncols; dst rows x npad (pad cols zeroed)
__global__ void split_pad_kernel(const float* __restrict__ src,
                                 __nv_bfloat16* __restrict__ hi,
                                 __nv_bfloat16* __restrict__ lo,
                                 int rows, int ncols, int npad)
{
    int i = blockIdx.x * blockDim.x + threadIdx.x;
    int per_row = npad >> 2;
    if (i >= rows * per_row) return;
    int r  = i / per_row;
    int c4 = (i - r * per_row) << 2;
    uint2 hv = {0, 0}, lv = {0, 0};
    if (c4 < ncols) {
        float4 v = *(const float4*)(src + (size_t)r * ncols + c4);
        split4(v, hv, lv);
    }
    *(uint2*)(hi + (size_t)r * npad + c4) = hv;
    *(uint2*)(lo + (size_t)r * npad + c4) = lv;
}

// ---------------------------------------------------------------------------
// MMA helpers
// ---------------------------------------------------------------------------
__device__ __forceinline__ uint32_t smem_u32(const void* p) {
    return (uint32_t)__cvta_generic_to_shared(p);
}
__device__ __forceinline__ void ldsm_x4(uint32_t* r, uint32_t addr) {
    asm volatile("ldmatrix.sync.aligned.m8n8.x4.shared.b16 {%0,%1,%2,%3}, [%4];"
        : "=r"(r[0]), "=r"(r[1]), "=r"(r[2]), "=r"(r[3]) : "r"(addr));
}
__device__ __forceinline__ void ldsm_x4_t(uint32_t* r, uint32_t addr) {
    asm volatile("ldmatrix.sync.aligned.m8n8.x4.trans.shared.b16 {%0,%1,%2,%3}, [%4];"
        : "=r"(r[0]), "=r"(r[1]), "=r"(r[2]), "=r"(r[3]) : "r"(addr));
}
__device__ __forceinline__ void mma_bf16(float* d, const uint32_t* a, const uint32_t* b) {
    asm volatile(
        "mma.sync.aligned.m16n8k16.row.col.f32.bf16.bf16.f32 "
        "{%0,%1,%2,%3}, {%4,%5,%6,%7}, {%8,%9}, {%0,%1,%2,%3};"
        : "+f"(d[0]), "+f"(d[1]), "+f"(d[2]), "+f"(d[3])
        : "r"(a[0]), "r"(a[1]), "r"(a[2]), "r"(a[3]), "r"(b[0]), "r"(b[1]));
}

// ---------------------------------------------------------------------------
// 3-pass split-bf16 GEMM: C = (Ahi+Alo)(Bhi+Blo), dropping lo*lo.
// Block tile 128x128x32, 256 threads (8 warps, 2x4 -> warp tile 64x32).
// B may be padded: Nb = padded row stride, Nc = true output width.
// Requires M%128==0, K%32==0, Nb%128==0.
// ---------------------------------------------------------------------------
#define GBM 128
#define GBN 128
#define GBK 32
#define SKA 40    // A smem row stride (halves): 80B  -> conflict-free ldmatrix
#define SKB 136   // B smem row stride (halves): 272B -> conflict-free ldmatrix

__global__ __launch_bounds__(256, 1) void gemm3_kernel(
    const __nv_bfloat16* __restrict__ Ahi, const __nv_bfloat16* __restrict__ Alo,
    const __nv_bfloat16* __restrict__ Bhi, const __nv_bfloat16* __restrict__ Blo,
    float* __restrict__ C, int M, int Nc, int Nb, int K)
{
    __shared__ __align__(16) __nv_bfloat16 sAhi[GBM * SKA];
    __shared__ __align__(16) __nv_bfloat16 sAlo[GBM * SKA];
    __shared__ __align__(16) __nv_bfloat16 sBhi[GBK * SKB];
    __shared__ __align__(16) __nv_bfloat16 sBlo[GBK * SKB];

    const int tid  = threadIdx.x;
    const int wid  = tid >> 5;
    const int lane = tid & 31;
    const int m0 = blockIdx.y * GBM;
    const int n0 = blockIdx.x * GBN;

    const int wm = (wid & 1) * 64;    // warp row offset
    const int wn = (wid >> 1) * 32;   // warp col offset

    // global load mapping
    const int a_r = tid >> 2;          // 0..63
    const int a_c = (tid & 3) * 8;     // halves within BK(32)
    const int b_r = tid >> 3;          // 0..31
    const int b_c = (tid & 7) * 16;    // halves within BN(128)

    const __nv_bfloat16* pAhi = Ahi + (size_t)(m0 + a_r) * K + a_c;
    const __nv_bfloat16* pAlo = Alo + (size_t)(m0 + a_r) * K + a_c;
    const __nv_bfloat16* pBhi = Bhi + (size_t)b_r * Nb + n0 + b_c;
    const __nv_bfloat16* pBlo = Blo + (size_t)b_r * Nb + n0 + b_c;

    uint4 rAh0 = *(const uint4*)pAhi;
    uint4 rAh1 = *(const uint4*)(pAhi + (size_t)64 * K);
    uint4 rAl0 = *(const uint4*)pAlo;
    uint4 rAl1 = *(const uint4*)(pAlo + (size_t)64 * K);
    uint4 rBh0 = *(const uint4*)pBhi;
    uint4 rBh1 = *(const uint4*)(pBhi + 8);
    uint4 rBl0 = *(const uint4*)pBlo;
    uint4 rBl1 = *(const uint4*)(pBlo + 8);

    float acc[4][4][4];
    #pragma unroll
    for (int i = 0; i < 4; i++)
        #pragma unroll
        for (int j = 0; j < 4; j++)
            #pragma unroll
            for (int k = 0; k < 4; k++) acc[i][j][k] = 0.0f;

    const int sa0 = a_r * SKA + a_c;
    const int sa1 = (a_r + 64) * SKA + a_c;
    const int sb0 = b_r * SKB + b_c;

    const int lm_row = lane & 15;
    const int lm_kch = (lane >> 4) * 8;
    const uint32_t sAhi_b = smem_u32(sAhi);
    const uint32_t sAlo_b = smem_u32(sAlo);
    const uint32_t sBhi_b = smem_u32(sBhi);
    const uint32_t sBlo_b = smem_u32(sBlo);

    const int ktiles = K / GBK;
    for (int kt = 0; kt < ktiles; kt++) {
        *(uint4*)&sAhi[sa0] = rAh0;
        *(uint4*)&sAhi[sa1] = rAh1;
        *(uint4*)&sAlo[sa0] = rAl0;
        *(uint4*)&sAlo[sa1] = rAl1;
        *(uint4*)&sBhi[sb0]     = rBh0;
        *(uint4*)&sBhi[sb0 + 8] = rBh1;
        *(uint4*)&sBlo[sb0]     = rBl0;
        *(uint4*)&sBlo[sb0 + 8] = rBl1;
        __syncthreads();

        if (kt + 1 < ktiles) {
            pAhi += GBK; pAlo += GBK;
            pBhi += (size_t)GBK * Nb; pBlo += (size_t)GBK * Nb;
            rAh0 = *(const uint4*)pAhi;
            rAh1 = *(const uint4*)(pAhi + (size_t)64 * K);
            rAl0 = *(const uint4*)pAlo;
            rAl1 = *(const uint4*)(pAlo + (size_t)64 * K);
            rBh0 = *(const uint4*)pBhi;
            rBh1 = *(const uint4*)(pBhi + 8);
            rBl0 = *(const uint4*)pBlo;
            rBl1 = *(const uint4*)(pBlo + 8);
        }

        #pragma unroll
        for (int ks = 0; ks < 2; ks++) {
            const int k0 = ks * 16;
            uint32_t ah[4][4], al[4][4], bh[2][4], bl[2][4];
            #pragma unroll
            for (int mi = 0; mi < 4; mi++) {
                uint32_t off = (uint32_t)((wm + mi * 16 + lm_row) * SKA + k0 + lm_kch) * 2;
                ldsm_x4(ah[mi], sAhi_b + off);
                ldsm_x4(al[mi], sAlo_b + off);
            }
            #pragma unroll
            for (int np = 0; np < 2; np++) {
                uint32_t off = (uint32_t)((k0 + lm_row) * SKB + wn + np * 16 + lm_kch) * 2;
                ldsm_x4_t(bh[np], sBhi_b + off);
                ldsm_x4_t(bl[np], sBlo_b + off);
            }
            #pragma unroll
            for (int mi = 0; mi < 4; mi++) {
                #pragma unroll
                for (int nj = 0; nj < 4; nj++) {
                    const uint32_t* bhp = &bh[nj >> 1][(nj & 1) * 2];
                    const uint32_t* blp = &bl[nj >> 1][(nj & 1) * 2];
                    mma_bf16(acc[mi][nj], ah[mi], bhp);   // hi*hi
                    mma_bf16(acc[mi][nj], ah[mi], blp);   // hi*lo
                    mma_bf16(acc[mi][nj], al[mi], bhp);   // lo*hi
                }
            }
        }
        __syncthreads();
    }

    const int er = lane >> 2;
    const int ec = (lane & 3) * 2;
    #pragma unroll
    for (int mi = 0; mi < 4; mi++) {
        #pragma unroll
        for (int nj = 0; nj < 4; nj++) {
            const int row = m0 + wm + mi * 16 + er;
            const int col = n0 + wn + nj * 8 + ec;
            if (col < Nc) {
                float2 v01; v01.x = acc[mi][nj][0]; v01.y = acc[mi][nj][1];
                float2 v23; v23.x = acc[mi][nj][2]; v23.y = acc[mi][nj][3];
                *(float2*)&C[(size_t)row * Nc + col]       = v01;
                *(float2*)&C[(size_t)(row + 8) * Nc + col] = v23;
            }
        }
    }
}

// ---------------------------------------------------------------------------
// RoPE in-place on qkv (q: 64 heads, k: 8 heads).
// ---------------------------------------------------------------------------
__global__ void rope_kernel(float* __restrict__ qkv, int n)
{
    int idx = blockIdx.x * blockDim.x + threadIdx.x;
    int total = n * (NHEADS + NKV) * (DHEAD / 2);
    if (idx >= total) return;

    int j   = idx & 31;
    int h   = (idx >> 5) % (NHEADS + NKV);
    int tok = idx / ((NHEADS + NKV) * 32);

    float* base;
    if (h < NHEADS)
        base = qkv + (size_t)tok * QKVW + h * DHEAD;
    else
        base = qkv + (size_t)tok * QKVW + NHEADS * DHEAD + (h - NHEADS) * DHEAD;

    float pos = (float)g_positions[tok];
    float inv_freq = powf(150000.0f, -((float)j) / 32.0f);
    float ang = pos * inv_freq;
    float s, c;
    sincosf(ang, &s, &c);

    float x1 = base[j];
    float x2 = base[j + 32];
    base[j]      = x1 * c - x2 * s;
    base[j + 32] = x2 * c + x1 * s;
}

// ---------------------------------------------------------------------------
// Sliding-window attention with sinks, 2 tokens per block.
// Grid: (n/2, NKV). Block: 256 threads. Writes bf16 hi/lo split directly.
// Union window = 129 slots: slot u <-> global token p0 - 127 + u, where
// p0 = position of even token. Token j (0/1) uses slots [j, j+128).
// Probs stored at index u = j + w, so PV indexes both tokens by u.
// ---------------------------------------------------------------------------
#define UNI 129

__global__ __launch_bounds__(256) void attn_kernel(
    const float* __restrict__ qkv, const float* __restrict__ sinks,
    __nv_bfloat16* __restrict__ out_hi, __nv_bfloat16* __restrict__ out_lo,
    int n)
{
    __shared__ float kbuf[UNI + 1][68];    // K then V; row 16B-aligned, 272B stride
    __shared__ float qs[2][GRP][DHEAD];    // scaled q
    __shared__ float sc[2][GRP][132];      // scores -> probs (index u)
    __shared__ float dinv[2][GRP];

    const int tok0 = blockIdx.x * 2;
    const int kv   = blockIdx.y;
    const int tid  = threadIdx.x;
    const int lane = tid & 31;
    const int wid  = tid >> 5;

    const int p0 = g_positions[tok0];

    // load q for both tokens (2*512 floats), pre-scaled
    for (int i = tid; i < 2 * GRP * DHEAD; i += 256) {
        int j = i >> 9, r = i & 511;
        qs[j][r >> 6][r & 63] =
            qkv[(size_t)(tok0 + j) * QKVW + (size_t)kv * GRP * DHEAD + r] * 0.125f;
    }

    // load K union window (129 rows x 64)
    for (int i = tid; i < UNI * (DHEAD / 4); i += 256) {
        int u  = i >> 4;
        int c4 = (i & 15) << 2;
        int t = p0 - (WIN - 1) + u;
        t = max(0, min(t, n - 1));
        float4 kd = *(const float4*)(qkv + (size_t)t * QKVW + NHEADS * DHEAD
                                     + (size_t)kv * DHEAD + c4);
        *(float4*)&kbuf[u][c4] = kd;
    }
    __syncthreads();

    // scores: thread u (< 129) computes dot(k[u], q[j][g]) for all j,g
    if (tid < UNI) {
        const int u = tid;
        float s[2][GRP];
        #pragma unroll
        for (int j = 0; j < 2; j++)
            #pragma unroll
            for (int g = 0; g < GRP; g++) s[j][g] = 0.0f;

        #pragma unroll 4
        for (int d4 = 0; d4 < DHEAD / 4; d4++) {
            float4 kd = *(const float4*)&kbuf[u][d4 * 4];
            #pragma unroll
            for (int j = 0; j < 2; j++)
                #pragma unroll
                for (int g = 0; g < GRP; g++) {
                    s[j][g] += kd.x * qs[j][g][d4 * 4 + 0];
                    s[j][g] += kd.y * qs[j][g][d4 * 4 + 1];
                    s[j][g] += kd.z * qs[j][g][d4 * 4 + 2];
                    s[j][g] += kd.w * qs[j][g][d4 * 4 + 3];
                }
        }

        const bool tvalid = (p0 - (WIN - 1) + u) >= 0;
        #pragma unroll
        for (int j = 0; j < 2; j++) {
            int w = u - j;
            bool inw = (w >= 0) && (w < WIN);
            float fill = inw ? (tvalid ? 0.0f : -INFINITY) : 0.0f;
            #pragma unroll
            for (int g = 0; g < GRP; g++)
                sc[j][g][u] = inw ? (tvalid ? s[j][g] : -INFINITY) : fill;
        }
    }
    __syncthreads();

    // softmax: warp wid handles (j,g) pairs p = 2*wid, 2*wid+1 (128 vals each)
    #pragma unroll
    for (int pp = 0; pp < 2; pp++) {
        int p = wid * 2 + pp;
        int j = p >> 3, g = p & 7;
        float vals[4];
        #pragma unroll
        for (int i = 0; i < 4; i++)
            vals[i] = sc[j][g][j + lane + i * 32];
        float m = fmaxf(fmaxf(vals[0], vals[1]), fmaxf(vals[2], vals[3]));
        #pragma unroll
        for (int off = 16; off; off >>= 1)
            m = fmaxf(m, __shfl_xor_sync(0xffffffffu, m, off));
        float snk = sinks[kv * GRP + g];
        m = fmaxf(m, snk);
        float ssum = 0.0f;
        #pragma unroll
        for (int i = 0; i < 4; i++) {
            float pv = expf(vals[i] - m);
            sc[j][g][j + lane + i * 32] = pv;
            ssum += pv;
        }
        #pragma unroll
        for (int off = 16; off; off >>= 1)
            ssum += __shfl_xor_sync(0xffffffffu, ssum, off);
        if (lane == 0)
            dinv[j][g] = 1.0f / (ssum + expf(snk - m));
    }

    // load V union window into kbuf (reuse) — safe: kbuf reads done pre-sync
    for (int i = tid; i < UNI * (DHEAD / 4); i += 256) {
        int u  = i >> 4;
        int c4 = (i & 15) << 2;
        int t = p0 - (WIN - 1) + u;
        t = max(0, min(t, n - 1));
        float4 vd = *(const float4*)(qkv + (size_t)t * QKVW
                                     + (NHEADS + NKV) * DHEAD
                                     + (size_t)kv * DHEAD + c4);
        *(float4*)&kbuf[u][c4] = vd;
    }
    __syncthreads();

    // PV: thread owns (g = tid>>5, d-pair = (tid&31)*2), both tokens
    {
        const int g  = tid >> 5;      // warp id = head in group
        const int d2 = (tid & 31) * 2;
        float a00 = 0.f, a01 = 0.f, a10 = 0.f, a11 = 0.f;
        #pragma unroll 4
        for (int u = 0; u < UNI; u++) {
            float2 vd = *(const float2*)&kbuf[u][d2];
            float p0j = sc[0][g][u];
            float p1j = sc[1][g][u];
            a00 += p0j * vd.x; a01 += p0j * vd.y;
            a10 += p1j * vd.x; a11 += p1j * vd.y;
        }
        float di0 = dinv[0][g], di1 = dinv[1][g];
        float o00 = a00 * di0, o01 = a01 * di0;
        float o10 = a10 * di1, o11 = a11 * di1;

        // write bf16 hi/lo split directly
        size_t base0 = (size_t)tok0 * AOW + ((size_t)kv * GRP + g) * DHEAD + d2;
        size_t base1 = base0 + AOW;
        __nv_bfloat16 h;
        h = __float2bfloat16(o00); out_hi[base0]   = h; out_lo[base0]   = __float2bfloat16(o00 - __bfloat162float(h));
        h = __float2bfloat16(o01); out_hi[base0+1] = h; out_lo[base0+1] = __float2bfloat16(o01 - __bfloat162float(h));
        h = __float2bfloat16(o10); out_hi[base1]   = h; out_lo[base1]   = __float2bfloat16(o10 - __bfloat162float(h));
        h = __float2bfloat16(o11); out_hi[base1+1] = h; out_lo[base1+1] = __float2bfloat16(o11 - __bfloat162float(h));
    }
}

// ---------------------------------------------------------------------------
extern "C" void kernel_launch(void* const* d_in, const int* in_sizes, int n_in,
                              void* d_out, int out_size)
{
    const float* hs    = (const float*)d_in[0];
    const float* wqkv  = (const float*)d_in[1];
    const float* wo    = (const float*)d_in[2];
    const float* sinks = (const float*)d_in[3];
    const void*  pos   = (const void*)d_in[4];
    float*       out   = (float*)d_out;

    const int n = in_sizes[0] / HDIM;   // 1024

    float* qkv_ptr;
    __nv_bfloat16 *ahi, *alo, *athi, *atlo, *wqh, *wql, *woh, *wol;
    cudaGetSymbolAddress((void**)&qkv_ptr,  g_qkv);
    cudaGetSymbolAddress((void**)&ahi,  g_ahi);
    cudaGetSymbolAddress((void**)&alo,  g_alo);
    cudaGetSymbolAddress((void**)&athi, g_athi);
    cudaGetSymbolAddress((void**)&atlo, g_atlo);
    cudaGetSymbolAddress((void**)&wqh,  g_wqh);
    cudaGetSymbolAddress((void**)&wql,  g_wql);
    cudaGetSymbolAddress((void**)&woh,  g_woh);
    cudaGetSymbolAddress((void**)&wol,  g_wol);

    // 0) normalize positions
    norm_pos_kernel<<<1, 1024>>>(pos, n);

    // 1) bf16 hi/lo splits (inputs + weights)
    {
        int n4 = (n * HDIM) / 4;
        split_kernel<<<(n4 + 255) / 256, 256>>>(hs, ahi, alo, n4);
        n4 = (HDIM * QKVW) / 4;
        split_kernel<<<(n4 + 255) / 256, 256>>>(wqkv, wqh, wql, n4);
        int tot = AOW * (WO_NPAD / 4);
        split_pad_kernel<<<(tot + 255) / 256, 256>>>(wo, woh, wol, AOW, HDIM, WO_NPAD);
    }

    // 2) qkv = hs @ Wqkv  (tensor core, 3-pass split-bf16)
    {
        dim3 grid(QKVW / GBN, n / GBM);
        gemm3_kernel<<<grid, 256>>>(ahi, alo, wqh, wql, qkv_ptr,
                                    n, QKVW, QKVW, HDIM);
    }

    // 3) RoPE in place on q and k
    {
        int total = n * (NHEADS + NKV) * (DHEAD / 2);
        rope_kernel<<<(total + 255) / 256, 256>>>(qkv_ptr, n);
    }

    // 4) attention (2 tokens/block), writes bf16 hi/lo directly
    {
        dim3 grid(n / 2, NKV);
        attn_kernel<<<grid, 256>>>(qkv_ptr, sinks, athi, atlo, n);
    }

    // 5) out = attn @ Wo  (Wo padded to 2944 cols; stores guarded)
    {
        dim3 grid(WO_NPAD / GBN, n / GBM);
        gemm3_kernel<<<grid, 256>>>(athi, atlo, woh, wol, out,
                                    n, HDIM, WO_NPAD, AOW);
    }
}

// round 5
// speedup vs baseline: 1.0376x; 1.0376x over previous
#include <cuda_runtime.h>
#include <cuda_bf16.h>
#include <math.h>
#include <stdint.h>

// Problem constants
#define HDIM   2880
#define NHEADS 64
#define NKV    8
#define DHEAD  64
#define GRP    8          // NHEADS / NKV
#define WIN    128
#define QKVW   5120       // (NHEADS + 2*NKV) * DHEAD
#define AOW    4096       // NHEADS * DHEAD
#define NMAX   1024
#define WO_NPAD 2944      // 23 * 128 (padded N for GEMM2)

// Scratch (device globals: allocation-free)
__device__ float g_qkv[NMAX * QKVW];   // 20 MB
__device__ int   g_positions[NMAX];

__device__ __align__(16) __nv_bfloat16 g_ahi[NMAX * HDIM];
__device__ __align__(16) __nv_bfloat16 g_alo[NMAX * HDIM];
__device__ __align__(16) __nv_bfloat16 g_athi[NMAX * AOW];
__device__ __align__(16) __nv_bfloat16 g_atlo[NMAX * AOW];
__device__ __align__(16) __nv_bfloat16 g_wqh[HDIM * QKVW];
__device__ __align__(16) __nv_bfloat16 g_wql[HDIM * QKVW];
__device__ __align__(16) __nv_bfloat16 g_woh[AOW * WO_NPAD];
__device__ __align__(16) __nv_bfloat16 g_wol[AOW * WO_NPAD];

// ---------------------------------------------------------------------------
// positions normalizer (int32 vs int64 robust; positions are arange here)
// ---------------------------------------------------------------------------
__global__ void norm_pos_kernel(const void* __restrict__ pos_raw, int n)
{
    const long long* p64 = (const long long*)pos_raw;
    const int*       p32 = (const int*)pos_raw;
    __shared__ int is64;
    if (threadIdx.x == 0) {
        long long v0 = p64[0];
        long long v1 = (n > 1) ? p64[1] : 1;
        is64 = (v0 == 0 && v1 == 1) ? 1 : 0;
    }
    __syncthreads();
    for (int i = threadIdx.x; i < n; i += blockDim.x)
        g_positions[i] = is64 ? (int)p64[i] : p32[i];
}

// ---------------------------------------------------------------------------
// fp32 -> bf16 hi/lo split (vectorized x4)
// ---------------------------------------------------------------------------
__device__ __forceinline__ void split4(float4 v, uint2& hv, uint2& lv)
{
    __nv_bfloat16 h0 = __float2bfloat16(v.x);
    __nv_bfloat16 h1 = __float2bfloat16(v.y);
    __nv_bfloat16 h2 = __float2bfloat16(v.z);
    __nv_bfloat16 h3 = __float2bfloat16(v.w);
    __nv_bfloat16 l0 = __float2bfloat16(v.x - __bfloat162float(h0));
    __nv_bfloat16 l1 = __float2bfloat16(v.y - __bfloat162float(h1));
    __nv_bfloat16 l2 = __float2bfloat16(v.z - __bfloat162float(h2));
    __nv_bfloat16 l3 = __float2bfloat16(v.w - __bfloat162float(h3));
    __nv_bfloat162 hp0 = __nv_bfloat162(h0, h1);
    __nv_bfloat162 hp1 = __nv_bfloat162(h2, h3);
    __nv_bfloat162 lp0 = __nv_bfloat162(l0, l1);
    __nv_bfloat162 lp1 = __nv_bfloat162(l2, l3);
    hv.x = *(uint32_t*)&hp0; hv.y = *(uint32_t*)&hp1;
    lv.x = *(uint32_t*)&lp0; lv.y = *(uint32_t*)&lp1;
}

__global__ void split_kernel(const float* __restrict__ src,
                             __nv_bfloat16* __restrict__ hi,
                             __nv_bfloat16* __restrict__ lo, int n4)
{
    int i = blockIdx.x * blockDim.x + threadIdx.x;
    if (i >= n4) return;
    float4 v = ((const float4*)src)[i];
    uint2 hv, lv;
    split4(v, hv, lv);
    ((uint2*)hi)[i] = hv;
    ((uint2*)lo)[i] = lv;
}

// padded split: src is rows x ncols; dst rows x npad (pad cols zeroed)
__global__ void split_pad_kernel(const float* __restrict__ src,
                                 __nv_bfloat16* __restrict__ hi,
                                 __nv_bfloat16* __restrict__ lo,
                                 int rows, int ncols, int npad)
{
    int i = blockIdx.x * blockDim.x + threadIdx.x;
    int per_row = npad >> 2;
    if (i >= rows * per_row) return;
    int r  = i / per_row;
    int c4 = (i - r * per_row) << 2;
    uint2 hv = {0, 0}, lv = {0, 0};
    if (c4 < ncols) {
        float4 v = *(const float4*)(src + (size_t)r * ncols + c4);
        split4(v, hv, lv);
    }
    *(uint2*)(hi + (size_t)r * npad + c4) = hv;
    *(uint2*)(lo + (size_t)r * npad + c4) = lv;
}

// ---------------------------------------------------------------------------
// MMA helpers
// ---------------------------------------------------------------------------
__device__ __forceinline__ uint32_t smem_u32(const void* p) {
    return (uint32_t)__cvta_generic_to_shared(p);
}
__device__ __forceinline__ void ldsm_x4(uint32_t* r, uint32_t addr) {
    asm volatile("ldmatrix.sync.aligned.m8n8.x4.shared.b16 {%0,%1,%2,%3}, [%4];"
        : "=r"(r[0]), "=r"(r[1]), "=r"(r[2]), "=r"(r[3]) : "r"(addr));
}
__device__ __forceinline__ void ldsm_x4_t(uint32_t* r, uint32_t addr) {
    asm volatile("ldmatrix.sync.aligned.m8n8.x4.trans.shared.b16 {%0,%1,%2,%3}, [%4];"
        : "=r"(r[0]), "=r"(r[1]), "=r"(r[2]), "=r"(r[3]) : "r"(addr));
}
__device__ __forceinline__ void mma_bf16(float* d, const uint32_t* a, const uint32_t* b) {
    asm volatile(
        "mma.sync.aligned.m16n8k16.row.col.f32.bf16.bf16.f32 "
        "{%0,%1,%2,%3}, {%4,%5,%6,%7}, {%8,%9}, {%0,%1,%2,%3};"
        : "+f"(d[0]), "+f"(d[1]), "+f"(d[2]), "+f"(d[3])
        : "r"(a[0]), "r"(a[1]), "r"(a[2]), "r"(a[3]), "r"(b[0]), "r"(b[1]));
}
__device__ __forceinline__ void cp16(uint32_t dst, const void* src) {
    asm volatile("cp.async.cg.shared.global [%0], [%1], 16;"
        :: "r"(dst), "l"(src));
}

// ---------------------------------------------------------------------------
// 3-pass split-bf16 GEMM with 4-stage cp.async pipeline.
// C = (Ahi+Alo)(Bhi+Blo), dropping lo*lo.
// Block tile 128x128x32, 256 threads (8 warps, 2x4 -> warp tile 64x32).
// Requires M%128==0, K%32==0, Nb%128==0.
// ---------------------------------------------------------------------------
#define GBM 128
#define GBN 128
#define GBK 32
#define SKA 40    // A smem row stride (halves): 80B  -> conflict-free ldmatrix
#define SKB 136   // B smem row stride (halves): 272B -> conflict-free ldmatrix
#define STAGES 4
#define OFF_ALO 10240
#define OFF_BHI 20480
#define OFF_BLO 29184
#define STAGE_BYTES 37888
#define GEMM_SMEM (STAGES * STAGE_BYTES)   // 151552

extern __shared__ char dsm[];

__device__ __forceinline__ void issue_stage(
    uint32_t stg,
    const __nv_bfloat16* __restrict__ Ahi, const __nv_bfloat16* __restrict__ Alo,
    const __nv_bfloat16* __restrict__ Bhi, const __nv_bfloat16* __restrict__ Blo,
    int tid, int m0, int n0, int kt, int K, int Nb)
{
    #pragma unroll
    for (int i = 0; i < 2; i++) {
        int id = tid + i * 256;
        int ar = id >> 2, ac = (id & 3) * 8;
        size_t aoff = (size_t)(m0 + ar) * K + kt * GBK + ac;
        cp16(stg + (uint32_t)(ar * SKA + ac) * 2, Ahi + aoff);
        cp16(stg + OFF_ALO + (uint32_t)(ar * SKA + ac) * 2, Alo + aoff);
        int br = id >> 4, bc = (id & 15) * 8;
        size_t boff = (size_t)(kt * GBK + br) * Nb + n0 + bc;
        cp16(stg + OFF_BHI + (uint32_t)(br * SKB + bc) * 2, Bhi + boff);
        cp16(stg + OFF_BLO + (uint32_t)(br * SKB + bc) * 2, Blo + boff);
    }
}

__global__ __launch_bounds__(256, 1) void gemm3_kernel(
    const __nv_bfloat16* __restrict__ Ahi, const __nv_bfloat16* __restrict__ Alo,
    const __nv_bfloat16* __restrict__ Bhi, const __nv_bfloat16* __restrict__ Blo,
    float* __restrict__ C, int M, int Nc, int Nb, int K)
{
    const int tid  = threadIdx.x;
    const int wid  = tid >> 5;
    const int lane = tid & 31;
    const int m0 = blockIdx.y * GBM;
    const int n0 = blockIdx.x * GBN;

    const int wm = (wid & 1) * 64;    // warp row offset
    const int wn = (wid >> 1) * 32;   // warp col offset

    const uint32_t sbase = smem_u32(dsm);

    float acc[4][4][4];
    #pragma unroll
    for (int i = 0; i < 4; i++)
        #pragma unroll
        for (int j = 0; j < 4; j++)
            #pragma unroll
            for (int k = 0; k < 4; k++) acc[i][j][k] = 0.0f;

    const int ktiles = K / GBK;

    // prologue: issue STAGES-1 stages
    #pragma unroll
    for (int s = 0; s < STAGES - 1; s++) {
        if (s < ktiles)
            issue_stage(sbase + s * STAGE_BYTES, Ahi, Alo, Bhi, Blo,
                        tid, m0, n0, s, K, Nb);
        asm volatile("cp.async.commit_group;");
    }

    const int lm_row = lane & 15;
    const int lm_kch = (lane >> 4) * 8;

    for (int kt = 0; kt < ktiles; kt++) {
        int pf = kt + STAGES - 1;
        if (pf < ktiles)
            issue_stage(sbase + (pf % STAGES) * STAGE_BYTES, Ahi, Alo, Bhi, Blo,
                        tid, m0, n0, pf, K, Nb);
        asm volatile("cp.async.commit_group;");
        asm volatile("cp.async.wait_group %0;" :: "n"(STAGES - 2));
        __syncthreads();

        const uint32_t stg = sbase + (kt % STAGES) * STAGE_BYTES;

        #pragma unroll
        for (int ks = 0; ks < 2; ks++) {
            const int k0 = ks * 16;
            uint32_t ah[4][4], al[4][4], bh[2][4], bl[2][4];
            #pragma unroll
            for (int mi = 0; mi < 4; mi++) {
                uint32_t off = (uint32_t)((wm + mi * 16 + lm_row) * SKA + k0 + lm_kch) * 2;
                ldsm_x4(ah[mi], stg + off);
                ldsm_x4(al[mi], stg + OFF_ALO + off);
            }
            #pragma unroll
            for (int np = 0; np < 2; np++) {
                uint32_t off = (uint32_t)((k0 + lm_row) * SKB + wn + np * 16 + lm_kch) * 2;
                ldsm_x4_t(bh[np], stg + OFF_BHI + off);
                ldsm_x4_t(bl[np], stg + OFF_BLO + off);
            }
            #pragma unroll
            for (int mi = 0; mi < 4; mi++) {
                #pragma unroll
                for (int nj = 0; nj < 4; nj++) {
                    const uint32_t* bhp = &bh[nj >> 1][(nj & 1) * 2];
                    const uint32_t* blp = &bl[nj >> 1][(nj & 1) * 2];
                    mma_bf16(acc[mi][nj], ah[mi], bhp);   // hi*hi
                    mma_bf16(acc[mi][nj], ah[mi], blp);   // hi*lo
                    mma_bf16(acc[mi][nj], al[mi], bhp);   // lo*hi
                }
            }
        }
        __syncthreads();
    }

    const int er = lane >> 2;
    const int ec = (lane & 3) * 2;
    #pragma unroll
    for (int mi = 0; mi < 4; mi++) {
        #pragma unroll
        for (int nj = 0; nj < 4; nj++) {
            const int row = m0 + wm + mi * 16 + er;
            const int col = n0 + wn + nj * 8 + ec;
            if (col < Nc) {
                float2 v01; v01.x = acc[mi][nj][0]; v01.y = acc[mi][nj][1];
                float2 v23; v23.x = acc[mi][nj][2]; v23.y = acc[mi][nj][3];
                *(float2*)&C[(size_t)row * Nc + col]       = v01;
                *(float2*)&C[(size_t)(row + 8) * Nc + col] = v23;
            }
        }
    }
}

// ---------------------------------------------------------------------------
// RoPE in-place on qkv (q: 64 heads, k: 8 heads).
// ---------------------------------------------------------------------------
__global__ void rope_kernel(float* __restrict__ qkv, int n)
{
    int idx = blockIdx.x * blockDim.x + threadIdx.x;
    int total = n * (NHEADS + NKV) * (DHEAD / 2);
    if (idx >= total) return;

    int j   = idx & 31;
    int h   = (idx >> 5) % (NHEADS + NKV);
    int tok = idx / ((NHEADS + NKV) * 32);

    float* base;
    if (h < NHEADS)
        base = qkv + (size_t)tok * QKVW + h * DHEAD;
    else
        base = qkv + (size_t)tok * QKVW + NHEADS * DHEAD + (h - NHEADS) * DHEAD;

    float pos = (float)g_positions[tok];
    float inv_freq = powf(150000.0f, -((float)j) / 32.0f);
    float ang = pos * inv_freq;
    float s, c;
    sincosf(ang, &s, &c);

    float x1 = base[j];
    float x2 = base[j + 32];
    base[j]      = x1 * c - x2 * s;
    base[j + 32] = x2 * c + x1 * s;
}

// ---------------------------------------------------------------------------
// Sliding-window attention with sinks, 2 tokens per block.
// Grid: (n/2, NKV). Block: 256 threads. Writes bf16 hi/lo split directly.
// ---------------------------------------------------------------------------
#define UNI 129

__global__ __launch_bounds__(256) void attn_kernel(
    const float* __restrict__ qkv, const float* __restrict__ sinks,
    __nv_bfloat16* __restrict__ out_hi, __nv_bfloat16* __restrict__ out_lo,
    int n)
{
    __shared__ float kbuf[UNI + 1][68];    // K then V
    __shared__ float qs[2][GRP][DHEAD];    // scaled q
    __shared__ float sc[2][GRP][132];      // scores -> probs (index u)
    __shared__ float dinv[2][GRP];

    const int tok0 = blockIdx.x * 2;
    const int kv   = blockIdx.y;
    const int tid  = threadIdx.x;
    const int lane = tid & 31;
    const int wid  = tid >> 5;

    const int p0 = g_positions[tok0];

    for (int i = tid; i < 2 * GRP * DHEAD; i += 256) {
        int j = i >> 9, r = i & 511;
        qs[j][r >> 6][r & 63] =
            qkv[(size_t)(tok0 + j) * QKVW + (size_t)kv * GRP * DHEAD + r] * 0.125f;
    }

    for (int i = tid; i < UNI * (DHEAD / 4); i += 256) {
        int u  = i >> 4;
        int c4 = (i & 15) << 2;
        int t = p0 - (WIN - 1) + u;
        t = max(0, min(t, n - 1));
        float4 kd = *(const float4*)(qkv + (size_t)t * QKVW + NHEADS * DHEAD
                                     + (size_t)kv * DHEAD + c4);
        *(float4*)&kbuf[u][c4] = kd;
    }
    __syncthreads();

    if (tid < UNI) {
        const int u = tid;
        float s[2][GRP];
        #pragma unroll
        for (int j = 0; j < 2; j++)
            #pragma unroll
            for (int g = 0; g < GRP; g++) s[j][g] = 0.0f;

        #pragma unroll 4
        for (int d4 = 0; d4 < DHEAD / 4; d4++) {
            float4 kd = *(const float4*)&kbuf[u][d4 * 4];
            #pragma unroll
            for (int j = 0; j < 2; j++)
                #pragma unroll
                for (int g = 0; g < GRP; g++) {
                    s[j][g] += kd.x * qs[j][g][d4 * 4 + 0];
                    s[j][g] += kd.y * qs[j][g][d4 * 4 + 1];
                    s[j][g] += kd.z * qs[j][g][d4 * 4 + 2];
                    s[j][g] += kd.w * qs[j][g][d4 * 4 + 3];
                }
        }

        const bool tvalid = (p0 - (WIN - 1) + u) >= 0;
        #pragma unroll
        for (int j = 0; j < 2; j++) {
            int w = u - j;
            bool inw = (w >= 0) && (w < WIN);
            #pragma unroll
            for (int g = 0; g < GRP; g++)
                sc[j][g][u] = inw ? (tvalid ? s[j][g] : -INFINITY) : 0.0f;
        }
    }
    __syncthreads();

    #pragma unroll
    for (int pp = 0; pp < 2; pp++) {
        int p = wid * 2 + pp;
        int j = p >> 3, g = p & 7;
        float vals[4];
        #pragma unroll
        for (int i = 0; i < 4; i++)
            vals[i] = sc[j][g][j + lane + i * 32];
        float m = fmaxf(fmaxf(vals[0], vals[1]), fmaxf(vals[2], vals[3]));
        #pragma unroll
        for (int off = 16; off; off >>= 1)
            m = fmaxf(m, __shfl_xor_sync(0xffffffffu, m, off));
        float snk = sinks[kv * GRP + g];
        m = fmaxf(m, snk);
        float ssum = 0.0f;
        #pragma unroll
        for (int i = 0; i < 4; i++) {
            float pv = expf(vals[i] - m);
            sc[j][g][j + lane + i * 32] = pv;
            ssum += pv;
        }
        #pragma unroll
        for (int off = 16; off; off >>= 1)
            ssum += __shfl_xor_sync(0xffffffffu, ssum, off);
        if (lane == 0)
            dinv[j][g] = 1.0f / (ssum + expf(snk - m));
    }

    for (int i = tid; i < UNI * (DHEAD / 4); i += 256) {
        int u  = i >> 4;
        int c4 = (i & 15) << 2;
        int t = p0 - (WIN - 1) + u;
        t = max(0, min(t, n - 1));
        float4 vd = *(const float4*)(qkv + (size_t)t * QKVW
                                     + (NHEADS + NKV) * DHEAD
                                     + (size_t)kv * DHEAD + c4);
        *(float4*)&kbuf[u][c4] = vd;
    }
    __syncthreads();

    {
        const int g  = tid >> 5;
        const int d2 = (tid & 31) * 2;
        float a00 = 0.f, a01 = 0.f, a10 = 0.f, a11 = 0.f;
        #pragma unroll 4
        for (int u = 0; u < UNI; u++) {
            float2 vd = *(const float2*)&kbuf[u][d2];
            float p0j = sc[0][g][u];
            float p1j = sc[1][g][u];
            a00 += p0j * vd.x; a01 += p0j * vd.y;
            a10 += p1j * vd.x; a11 += p1j * vd.y;
        }
        float di0 = dinv[0][g], di1 = dinv[1][g];
        float o00 = a00 * di0, o01 = a01 * di0;
        float o10 = a10 * di1, o11 = a11 * di1;

        size_t base0 = (size_t)tok0 * AOW + ((size_t)kv * GRP + g) * DHEAD + d2;
        size_t base1 = base0 + AOW;
        __nv_bfloat16 h;
        h = __float2bfloat16(o00); out_hi[base0]   = h; out_lo[base0]   = __float2bfloat16(o00 - __bfloat162float(h));
        h = __float2bfloat16(o01); out_hi[base0+1] = h; out_lo[base0+1] = __float2bfloat16(o01 - __bfloat162float(h));
        h = __float2bfloat16(o10); out_hi[base1]   = h; out_lo[base1]   = __float2bfloat16(o10 - __bfloat162float(h));
        h = __float2bfloat16(o11); out_hi[base1+1] = h; out_lo[base1+1] = __float2bfloat16(o11 - __bfloat162float(h));
    }
}

// ---------------------------------------------------------------------------
extern "C" void kernel_launch(void* const* d_in, const int* in_sizes, int n_in,
                              void* d_out, int out_size)
{
    const float* hs    = (const float*)d_in[0];
    const float* wqkv  = (const float*)d_in[1];
    const float* wo    = (const float*)d_in[2];
    const float* sinks = (const float*)d_in[3];
    const void*  pos   = (const void*)d_in[4];
    float*       out   = (float*)d_out;

    const int n = in_sizes[0] / HDIM;   // 1024

    float* qkv_ptr;
    __nv_bfloat16 *ahi, *alo, *athi, *atlo, *wqh, *wql, *woh, *wol;
    cudaGetSymbolAddress((void**)&qkv_ptr,  g_qkv);
    cudaGetSymbolAddress((void**)&ahi,  g_ahi);
    cudaGetSymbolAddress((void**)&alo,  g_alo);
    cudaGetSymbolAddress((void**)&athi, g_athi);
    cudaGetSymbolAddress((void**)&atlo, g_atlo);
    cudaGetSymbolAddress((void**)&wqh,  g_wqh);
    cudaGetSymbolAddress((void**)&wql,  g_wql);
    cudaGetSymbolAddress((void**)&woh,  g_woh);
    cudaGetSymbolAddress((void**)&wol,  g_wol);

    cudaFuncSetAttribute(gemm3_kernel,
                         cudaFuncAttributeMaxDynamicSharedMemorySize, GEMM_SMEM);

    // 0) normalize positions
    norm_pos_kernel<<<1, 1024>>>(pos, n);

    // 1) bf16 hi/lo splits (inputs + weights)
    {
        int n4 = (n * HDIM) / 4;
        split_kernel<<<(n4 + 255) / 256, 256>>>(hs, ahi, alo, n4);
        n4 = (HDIM * QKVW) / 4;
        split_kernel<<<(n4 + 255) / 256, 256>>>(wqkv, wqh, wql, n4);
        int tot = AOW * (WO_NPAD / 4);
        split_pad_kernel<<<(tot + 255) / 256, 256>>>(wo, woh, wol, AOW, HDIM, WO_NPAD);
    }

    // 2) qkv = hs @ Wqkv
    {
        dim3 grid(QKVW / GBN, n / GBM);
        gemm3_kernel<<<grid, 256, GEMM_SMEM>>>(ahi, alo, wqh, wql, qkv_ptr,
                                               n, QKVW, QKVW, HDIM);
    }

    // 3) RoPE in place on q and k
    {
        int total = n * (NHEADS + NKV) * (DHEAD / 2);
        rope_kernel<<<(total + 255) / 256, 256>>>(qkv_ptr, n);
    }

    // 4) attention (2 tokens/block), writes bf16 hi/lo directly
    {
        dim3 grid(n / 2, NKV);
        attn_kernel<<<grid, 256>>>(qkv_ptr, sinks, athi, atlo, n);
    }

    // 5) out = attn @ Wo  (Wo padded to 2944 cols; stores guarded)
    {
        dim3 grid(WO_NPAD / GBN, n / GBM);
        gemm3_kernel<<<grid, 256, GEMM_SMEM>>>(athi, atlo, woh, wol, out,
                                               n, HDIM, WO_NPAD, AOW);
    }
}

// round 7
// speedup vs baseline: 1.1597x; 1.1176x over previous
#include <cuda_runtime.h>
#include <cuda_bf16.h>
#include <math.h>
#include <stdint.h>

// Problem constants
#define HDIM   2880
#define NHEADS 64
#define NKV    8
#define DHEAD  64
#define GRP    8          // NHEADS / NKV
#define WIN    128
#define QKVW   5120       // (NHEADS + 2*NKV) * DHEAD
#define AOW    4096       // NHEADS * DHEAD
#define NMAX   1024

// Scratch (device globals: allocation-free)
__device__ float g_qkv[NMAX * QKVW];   // 20 MB
__device__ int   g_positions[NMAX];

__device__ __align__(16) __nv_bfloat16 g_ahi[NMAX * HDIM];
__device__ __align__(16) __nv_bfloat16 g_alo[NMAX * HDIM];
__device__ __align__(16) __nv_bfloat16 g_athi[NMAX * AOW];
__device__ __align__(16) __nv_bfloat16 g_atlo[NMAX * AOW];
__device__ __align__(16) __nv_bfloat16 g_wqh[HDIM * QKVW];
__device__ __align__(16) __nv_bfloat16 g_wql[HDIM * QKVW];
__device__ __align__(16) __nv_bfloat16 g_woh[AOW * HDIM];
__device__ __align__(16) __nv_bfloat16 g_wol[AOW * HDIM];

// ---------------------------------------------------------------------------
// positions normalizer (int32 vs int64 robust; positions are arange here)
// ---------------------------------------------------------------------------
__global__ void norm_pos_kernel(const void* __restrict__ pos_raw, int n)
{
    const long long* p64 = (const long long*)pos_raw;
    const int*       p32 = (const int*)pos_raw;
    __shared__ int is64;
    if (threadIdx.x == 0) {
        long long v0 = p64[0];
        long long v1 = (n > 1) ? p64[1] : 1;
        is64 = (v0 == 0 && v1 == 1) ? 1 : 0;
    }
    __syncthreads();
    for (int i = threadIdx.x; i < n; i += blockDim.x)
        g_positions[i] = is64 ? (int)p64[i] : p32[i];
}

// ---------------------------------------------------------------------------
// fp32 -> bf16 hi/lo split (vectorized x4)
// ---------------------------------------------------------------------------
__device__ __forceinline__ void split4(float4 v, uint2& hv, uint2& lv)
{
    __nv_bfloat16 h0 = __float2bfloat16(v.x);
    __nv_bfloat16 h1 = __float2bfloat16(v.y);
    __nv_bfloat16 h2 = __float2bfloat16(v.z);
    __nv_bfloat16 h3 = __float2bfloat16(v.w);
    __nv_bfloat16 l0 = __float2bfloat16(v.x - __bfloat162float(h0));
    __nv_bfloat16 l1 = __float2bfloat16(v.y - __bfloat162float(h1));
    __nv_bfloat16 l2 = __float2bfloat16(v.z - __bfloat162float(h2));
    __nv_bfloat16 l3 = __float2bfloat16(v.w - __bfloat162float(h3));
    __nv_bfloat162 hp0 = __nv_bfloat162(h0, h1);
    __nv_bfloat162 hp1 = __nv_bfloat162(h2, h3);
    __nv_bfloat162 lp0 = __nv_bfloat162(l0, l1);
    __nv_bfloat162 lp1 = __nv_bfloat162(l2, l3);
    hv.x = *(uint32_t*)&hp0; hv.y = *(uint32_t*)&hp1;
    lv.x = *(uint32_t*)&lp0; lv.y = *(uint32_t*)&lp1;
}

__global__ void split_kernel(const float* __restrict__ src,
                             __nv_bfloat16* __restrict__ hi,
                             __nv_bfloat16* __restrict__ lo, int n4)
{
    int i = blockIdx.x * blockDim.x + threadIdx.x;
    if (i >= n4) return;
    float4 v = ((const float4*)src)[i];
    uint2 hv, lv;
    split4(v, hv, lv);
    ((uint2*)hi)[i] = hv;
    ((uint2*)lo)[i] = lv;
}

// ---------------------------------------------------------------------------
// MMA helpers
// ---------------------------------------------------------------------------
__device__ __forceinline__ uint32_t smem_u32(const void* p) {
    return (uint32_t)__cvta_generic_to_shared(p);
}
__device__ __forceinline__ void ldsm_x4(uint32_t* r, uint32_t addr) {
    asm volatile("ldmatrix.sync.aligned.m8n8.x4.shared.b16 {%0,%1,%2,%3}, [%4];"
        : "=r"(r[0]), "=r"(r[1]), "=r"(r[2]), "=r"(r[3]) : "r"(addr));
}
__device__ __forceinline__ void ldsm_x4_t(uint32_t* r, uint32_t addr) {
    asm volatile("ldmatrix.sync.aligned.m8n8.x4.trans.shared.b16 {%0,%1,%2,%3}, [%4];"
        : "=r"(r[0]), "=r"(r[1]), "=r"(r[2]), "=r"(r[3]) : "r"(addr));
}
__device__ __forceinline__ void mma_bf16(float* d, const uint32_t* a, const uint32_t* b) {
    asm volatile(
        "mma.sync.aligned.m16n8k16.row.col.f32.bf16.bf16.f32 "
        "{%0,%1,%2,%3}, {%4,%5,%6,%7}, {%8,%9}, {%0,%1,%2,%3};"
        : "+f"(d[0]), "+f"(d[1]), "+f"(d[2]), "+f"(d[3])
        : "r"(a[0]), "r"(a[1]), "r"(a[2]), "r"(a[3]), "r"(b[0]), "r"(b[1]));
}
__device__ __forceinline__ void cp16(uint32_t dst, const void* src) {
    asm volatile("cp.async.cg.shared.global [%0], [%1], 16;"
        :: "r"(dst), "l"(src));
}

// ---------------------------------------------------------------------------
// 3-pass split-bf16 GEMM, 3-stage cp.async pipeline, 2 CTAs/SM.
// C[M,N] = (Ahi+Alo)(Bhi+Blo), dropping lo*lo.  A [M][K], B [K][N] row-major.
// Block tile 128 x TN_ x 32; warps 2 x (TN_/32), warp tile 64x32.
// Requires M%128==0, N%TN_==0, K%32==0.
// ---------------------------------------------------------------------------
#define SKA 40   // A smem row stride (halves): 80B, 5 granules (coprime 8)

extern __shared__ char dsm[];

template<int TN_>
__global__ __launch_bounds__(TN_ * 2, 2) void gemm3p_kernel(
    const __nv_bfloat16* __restrict__ Ahi, const __nv_bfloat16* __restrict__ Alo,
    const __nv_bfloat16* __restrict__ Bhi, const __nv_bfloat16* __restrict__ Blo,
    float* __restrict__ C, int M, int N, int K)
{
    constexpr int NT      = TN_ * 2;          // threads (128 or 192)
    constexpr int SKB_    = TN_ + 8;          // B smem row stride (halves)
    constexpr uint32_t OFF_ALO = 10240;       // 128*SKA*2
    constexpr uint32_t OFF_BHI = 20480;
    constexpr uint32_t OFF_BLO = 20480u + 32u * SKB_ * 2u;
    constexpr uint32_t STG     = 20480u + 64u * SKB_ * 2u;
    constexpr int BGRAN   = 32 * (TN_ / 8);   // B 16B-granules per split

    const int tid  = threadIdx.x;
    const int wid  = tid >> 5;
    const int lane = tid & 31;
    const int m0 = blockIdx.y * 128;
    const int n0 = blockIdx.x * TN_;

    const int wm = (wid & 1) * 64;
    const int wn = (wid >> 1) * 32;

    const uint32_t sb = smem_u32(dsm);

    float acc[4][4][4];
    #pragma unroll
    for (int i = 0; i < 4; i++)
        #pragma unroll
        for (int j = 0; j < 4; j++)
            #pragma unroll
            for (int k = 0; k < 4; k++) acc[i][j][k] = 0.0f;

    const int nk = K / 32;

    auto issue = [&](int slot, int kc) {
        const uint32_t s = sb + (uint32_t)slot * STG;
        #pragma unroll 2
        for (int i = tid; i < 512; i += NT) {          // A: 128 rows x 4 granules
            int r = i >> 2, c = i & 3;
            uint32_t off = (uint32_t)(r * 80 + c * 16);
            size_t g = (size_t)(m0 + r) * K + (size_t)kc * 32 + c * 8;
            cp16(s + off, Ahi + g);
            cp16(s + OFF_ALO + off, Alo + g);
        }
        #pragma unroll 2
        for (int i = tid; i < BGRAN; i += NT) {        // B: 32 rows x TN_/8 granules
            int r = i / (TN_ / 8), c = i % (TN_ / 8);
            uint32_t off = (uint32_t)(r * (SKB_ * 2) + c * 16);
            size_t g = (size_t)(kc * 32 + r) * N + n0 + c * 8;
            cp16(s + OFF_BHI + off, Bhi + g);
            cp16(s + OFF_BLO + off, Blo + g);
        }
    };

    // prologue: stages 0 and 1
    issue(0, 0);
    asm volatile("cp.async.commit_group;");
    if (nk > 1) issue(1, 1);
    asm volatile("cp.async.commit_group;");

    const int lm_row = lane & 15;
    const int lm_kch = (lane >> 4) * 8;

    int slot = 0;
    for (int kt = 0; kt < nk; kt++) {
        if (kt + 2 < nk) {
            int ps = slot + 2; if (ps >= 3) ps -= 3;
            issue(ps, kt + 2);
        }
        asm volatile("cp.async.commit_group;");
        asm volatile("cp.async.wait_group 2;");
        __syncthreads();

        const uint32_t stg = sb + (uint32_t)slot * STG;

        #pragma unroll
        for (int ks = 0; ks < 2; ks++) {
            const int k0 = ks * 16;
            uint32_t ah[4][4], al[4][4], bh[2][4], bl[2][4];
            #pragma unroll
            for (int mi = 0; mi < 4; mi++) {
                uint32_t off = (uint32_t)((wm + mi * 16 + lm_row) * 80
                                          + (k0 + lm_kch) * 2);
                ldsm_x4(ah[mi], stg + off);
                ldsm_x4(al[mi], stg + OFF_ALO + off);
            }
            #pragma unroll
            for (int np = 0; np < 2; np++) {
                uint32_t off = (uint32_t)((k0 + lm_row) * (SKB_ * 2)
                                          + (wn + np * 16 + lm_kch) * 2);
                ldsm_x4_t(bh[np], stg + OFF_BHI + off);
                ldsm_x4_t(bl[np], stg + OFF_BLO + off);
            }
            #pragma unroll
            for (int mi = 0; mi < 4; mi++) {
                #pragma unroll
                for (int nj = 0; nj < 4; nj++) {
                    const uint32_t* bhp = &bh[nj >> 1][(nj & 1) * 2];
                    const uint32_t* blp = &bl[nj >> 1][(nj & 1) * 2];
                    mma_bf16(acc[mi][nj], ah[mi], bhp);   // hi*hi
                    mma_bf16(acc[mi][nj], ah[mi], blp);   // hi*lo
                    mma_bf16(acc[mi][nj], al[mi], bhp);   // lo*hi
                }
            }
        }
        __syncthreads();   // all warps done reading this stage
        slot++; if (slot >= 3) slot = 0;
    }

    const int er = lane >> 2;
    const int ec = (lane & 3) * 2;
    #pragma unroll
    for (int mi = 0; mi < 4; mi++) {
        #pragma unroll
        for (int nj = 0; nj < 4; nj++) {
            const int row = m0 + wm + mi * 16 + er;
            const int col = n0 + wn + nj * 8 + ec;
            float2 v01; v01.x = acc[mi][nj][0]; v01.y = acc[mi][nj][1];
            float2 v23; v23.x = acc[mi][nj][2]; v23.y = acc[mi][nj][3];
            *(float2*)&C[(size_t)row * N + col]       = v01;
            *(float2*)&C[(size_t)(row + 8) * N + col] = v23;
        }
    }
}

#define SMEM64 (3 * (20480 + 64 * 72 * 2))    // 89088
#define SMEM96 (3 * (20480 + 64 * 104 * 2))   // 101376

// ---------------------------------------------------------------------------
// RoPE in-place on qkv (q: 64 heads, k: 8 heads).
// ---------------------------------------------------------------------------
__global__ void rope_kernel(float* __restrict__ qkv, int n)
{
    int idx = blockIdx.x * blockDim.x + threadIdx.x;
    int total = n * (NHEADS + NKV) * (DHEAD / 2);
    if (idx >= total) return;

    int j   = idx & 31;
    int h   = (idx >> 5) % (NHEADS + NKV);
    int tok = idx / ((NHEADS + NKV) * 32);

    float* base;
    if (h < NHEADS)
        base = qkv + (size_t)tok * QKVW + h * DHEAD;
    else
        base = qkv + (size_t)tok * QKVW + NHEADS * DHEAD + (h - NHEADS) * DHEAD;

    float pos = (float)g_positions[tok];
    float inv_freq = powf(150000.0f, -((float)j) / 32.0f);
    float ang = pos * inv_freq;
    float s, c;
    sincosf(ang, &s, &c);

    float x1 = base[j];
    float x2 = base[j + 32];
    base[j]      = x1 * c - x2 * s;
    base[j + 32] = x2 * c + x1 * s;
}

// ---------------------------------------------------------------------------
// Sliding-window attention with sinks, 2 tokens per block.
// Grid: (n/2, NKV). Block: 256 threads. Writes bf16 hi/lo split directly.
// ---------------------------------------------------------------------------
#define UNI 129

__global__ __launch_bounds__(256) void attn_kernel(
    const float* __restrict__ qkv, const float* __restrict__ sinks,
    __nv_bfloat16* __restrict__ out_hi, __nv_bfloat16* __restrict__ out_lo,
    int n)
{
    __shared__ float kbuf[UNI + 1][68];    // K then V
    __shared__ float qs[2][GRP][DHEAD];    // scaled q
    __shared__ float sc[2][GRP][132];      // scores -> probs (index u)
    __shared__ float dinv[2][GRP];

    const int tok0 = blockIdx.x * 2;
    const int kv   = blockIdx.y;
    const int tid  = threadIdx.x;
    const int lane = tid & 31;
    const int wid  = tid >> 5;

    const int p0 = g_positions[tok0];

    for (int i = tid; i < 2 * GRP * DHEAD; i += 256) {
        int j = i >> 9, r = i & 511;
        qs[j][r >> 6][r & 63] =
            qkv[(size_t)(tok0 + j) * QKVW + (size_t)kv * GRP * DHEAD + r] * 0.125f;
    }

    for (int i = tid; i < UNI * (DHEAD / 4); i += 256) {
        int u  = i >> 4;
        int c4 = (i & 15) << 2;
        int t = p0 - (WIN - 1) + u;
        t = max(0, min(t, n - 1));
        float4 kd = *(const float4*)(qkv + (size_t)t * QKVW + NHEADS * DHEAD
                                     + (size_t)kv * DHEAD + c4);
        *(float4*)&kbuf[u][c4] = kd;
    }
    __syncthreads();

    if (tid < UNI) {
        const int u = tid;
        float s[2][GRP];
        #pragma unroll
        for (int j = 0; j < 2; j++)
            #pragma unroll
            for (int g = 0; g < GRP; g++) s[j][g] = 0.0f;

        #pragma unroll 4
        for (int d4 = 0; d4 < DHEAD / 4; d4++) {
            float4 kd = *(const float4*)&kbuf[u][d4 * 4];
            #pragma unroll
            for (int j = 0; j < 2; j++)
                #pragma unroll
                for (int g = 0; g < GRP; g++) {
                    s[j][g] += kd.x * qs[j][g][d4 * 4 + 0];
                    s[j][g] += kd.y * qs[j][g][d4 * 4 + 1];
                    s[j][g] += kd.z * qs[j][g][d4 * 4 + 2];
                    s[j][g] += kd.w * qs[j][g][d4 * 4 + 3];
                }
        }

        const bool tvalid = (p0 - (WIN - 1) + u) >= 0;
        #pragma unroll
        for (int j = 0; j < 2; j++) {
            int w = u - j;
            bool inw = (w >= 0) && (w < WIN);
            #pragma unroll
            for (int g = 0; g < GRP; g++)
                sc[j][g][u] = inw ? (tvalid ? s[j][g] : -INFINITY) : 0.0f;
        }
    }
    __syncthreads();

    #pragma unroll
    for (int pp = 0; pp < 2; pp++) {
        int p = wid * 2 + pp;
        int j = p >> 3, g = p & 7;
        float vals[4];
        #pragma unroll
        for (int i = 0; i < 4; i++)
            vals[i] = sc[j][g][j + lane + i * 32];
        float m = fmaxf(fmaxf(vals[0], vals[1]), fmaxf(vals[2], vals[3]));
        #pragma unroll
        for (int off = 16; off; off >>= 1)
            m = fmaxf(m, __shfl_xor_sync(0xffffffffu, m, off));
        float snk = sinks[kv * GRP + g];
        m = fmaxf(m, snk);
        float ssum = 0.0f;
        #pragma unroll
        for (int i = 0; i < 4; i++) {
            float pv = expf(vals[i] - m);
            sc[j][g][j + lane + i * 32] = pv;
            ssum += pv;
        }
        #pragma unroll
        for (int off = 16; off; off >>= 1)
            ssum += __shfl_xor_sync(0xffffffffu, ssum, off);
        if (lane == 0)
            dinv[j][g] = 1.0f / (ssum + expf(snk - m));
    }

    for (int i = tid; i < UNI * (DHEAD / 4); i += 256) {
        int u  = i >> 4;
        int c4 = (i & 15) << 2;
        int t = p0 - (WIN - 1) + u;
        t = max(0, min(t, n - 1));
        float4 vd = *(const float4*)(qkv + (size_t)t * QKVW
                                     + (NHEADS + NKV) * DHEAD
                                     + (size_t)kv * DHEAD + c4);
        *(float4*)&kbuf[u][c4] = vd;
    }
    __syncthreads();

    {
        const int g  = tid >> 5;
        const int d2 = (tid & 31) * 2;
        float a00 = 0.f, a01 = 0.f, a10 = 0.f, a11 = 0.f;
        #pragma unroll 4
        for (int u = 0; u < UNI; u++) {
            float2 vd = *(const float2*)&kbuf[u][d2];
            float p0j = sc[0][g][u];
            float p1j = sc[1][g][u];
            a00 += p0j * vd.x; a01 += p0j * vd.y;
            a10 += p1j * vd.x; a11 += p1j * vd.y;
        }
        float di0 = dinv[0][g], di1 = dinv[1][g];
        float o00 = a00 * di0, o01 = a01 * di0;
        float o10 = a10 * di1, o11 = a11 * di1;

        size_t base0 = (size_t)tok0 * AOW + ((size_t)kv * GRP + g) * DHEAD + d2;
        size_t base1 = base0 + AOW;
        __nv_bfloat16 h;
        h = __float2bfloat16(o00); out_hi[base0]   = h; out_lo[base0]   = __float2bfloat16(o00 - __bfloat162float(h));
        h = __float2bfloat16(o01); out_hi[base0+1] = h; out_lo[base0+1] = __float2bfloat16(o01 - __bfloat162float(h));
        h = __float2bfloat16(o10); out_hi[base1]   = h; out_lo[base1]   = __float2bfloat16(o10 - __bfloat162float(h));
        h = __float2bfloat16(o11); out_hi[base1+1] = h; out_lo[base1+1] = __float2bfloat16(o11 - __bfloat162float(h));
    }
}

// ---------------------------------------------------------------------------
extern "C" void kernel_launch(void* const* d_in, const int* in_sizes, int n_in,
                              void* d_out, int out_size)
{
    const float* hs    = (const float*)d_in[0];
    const float* wqkv  = (const float*)d_in[1];
    const float* wo    = (const float*)d_in[2];
    const float* sinks = (const float*)d_in[3];
    const void*  pos   = (const void*)d_in[4];
    float*       out   = (float*)d_out;

    const int n = in_sizes[0] / HDIM;   // 1024

    float* qkv_ptr;
    __nv_bfloat16 *ahi, *alo, *athi, *atlo, *wqh, *wql, *woh, *wol;
    cudaGetSymbolAddress((void**)&qkv_ptr,  g_qkv);
    cudaGetSymbolAddress((void**)&ahi,  g_ahi);
    cudaGetSymbolAddress((void**)&alo,  g_alo);
    cudaGetSymbolAddress((void**)&athi, g_athi);
    cudaGetSymbolAddress((void**)&atlo, g_atlo);
    cudaGetSymbolAddress((void**)&wqh,  g_wqh);
    cudaGetSymbolAddress((void**)&wql,  g_wql);
    cudaGetSymbolAddress((void**)&woh,  g_woh);
    cudaGetSymbolAddress((void**)&wol,  g_wol);

    cudaFuncSetAttribute(gemm3p_kernel<64>,
                         cudaFuncAttributeMaxDynamicSharedMemorySize, SMEM64);
    cudaFuncSetAttribute(gemm3p_kernel<96>,
                         cudaFuncAttributeMaxDynamicSharedMemorySize, SMEM96);

    // 0) normalize positions
    norm_pos_kernel<<<1, 1024>>>(pos, n);

    // 1) bf16 hi/lo splits (inputs + weights, no padding needed)
    {
        int n4 = (n * HDIM) / 4;
        split_kernel<<<(n4 + 255) / 256, 256>>>(hs, ahi, alo, n4);
        n4 = (HDIM * QKVW) / 4;
        split_kernel<<<(n4 + 255) / 256, 256>>>(wqkv, wqh, wql, n4);
        n4 = (AOW * HDIM) / 4;
        split_kernel<<<(n4 + 255) / 256, 256>>>(wo, woh, wol, n4);
    }

    // 2) qkv = hs @ Wqkv   (N tile 64: 5120 = 80*64)
    {
        dim3 grid(QKVW / 64, n / 128);
        gemm3p_kernel<64><<<grid, 128, SMEM64>>>(ahi, alo, wqh, wql, qkv_ptr,
                                                 n, QKVW, HDIM);
    }

    // 3) RoPE in place on q and k
    {
        int total = n * (NHEADS + NKV) * (DHEAD / 2);
        rope_kernel<<<(total + 255) / 256, 256>>>(qkv_ptr, n);
    }

    // 4) attention (2 tokens/block), writes bf16 hi/lo directly
    {
        dim3 grid(n / 2, NKV);
        attn_kernel<<<grid, 256>>>(qkv_ptr, sinks, athi, atlo, n);
    }

    // 5) out = attn @ Wo   (N tile 96: 2880 = 30*96, single wave)
    {
        dim3 grid(HDIM / 96, n / 128);
        gemm3p_kernel<96><<<grid, 192, SMEM96>>>(athi, atlo, woh, wol, out,
                                                 n, HDIM, AOW);
    }
}

// round 8
// speedup vs baseline: 1.3186x; 1.1370x over previous
#include <cuda_runtime.h>
#include <cuda_bf16.h>
#include <cuda_fp16.h>
#include <math.h>
#include <stdint.h>

// Problem constants
#define HDIM   2880
#define NHEADS 64
#define NKV    8
#define DHEAD  64
#define GRP    8          // NHEADS / NKV
#define WIN    128
#define QKVW   5120       // (NHEADS + 2*NKV) * DHEAD
#define AOW    4096       // NHEADS * DHEAD
#define NMAX   1024

// Scratch (device globals: allocation-free)
__device__ float g_qkv[NMAX * QKVW];   // 20 MB
__device__ int   g_positions[NMAX];

__device__ __align__(16) __nv_bfloat16 g_ahi[NMAX * HDIM];
__device__ __align__(16) __nv_bfloat16 g_alo[NMAX * HDIM];
__device__ __align__(16) __half        g_athi[NMAX * AOW];   // fp16 for GEMM2
__device__ __align__(16) __half        g_atlo[NMAX * AOW];
__device__ __align__(16) __nv_bfloat16 g_wqh[HDIM * QKVW];
__device__ __align__(16) __nv_bfloat16 g_wql[HDIM * QKVW];
__device__ __align__(16) __half        g_woh[AOW * HDIM];    // single fp16 Wo

// ---------------------------------------------------------------------------
// positions normalizer (int32 vs int64 robust; positions are arange here)
// ---------------------------------------------------------------------------
__global__ void norm_pos_kernel(const void* __restrict__ pos_raw, int n)
{
    const long long* p64 = (const long long*)pos_raw;
    const int*       p32 = (const int*)pos_raw;
    __shared__ int is64;
    if (threadIdx.x == 0) {
        long long v0 = p64[0];
        long long v1 = (n > 1) ? p64[1] : 1;
        is64 = (v0 == 0 && v1 == 1) ? 1 : 0;
    }
    __syncthreads();
    for (int i = threadIdx.x; i < n; i += blockDim.x)
        g_positions[i] = is64 ? (int)p64[i] : p32[i];
}

// ---------------------------------------------------------------------------
// fp32 -> bf16 hi/lo split (vectorized x4)
// ---------------------------------------------------------------------------
__device__ __forceinline__ void split4(float4 v, uint2& hv, uint2& lv)
{
    __nv_bfloat16 h0 = __float2bfloat16(v.x);
    __nv_bfloat16 h1 = __float2bfloat16(v.y);
    __nv_bfloat16 h2 = __float2bfloat16(v.z);
    __nv_bfloat16 h3 = __float2bfloat16(v.w);
    __nv_bfloat16 l0 = __float2bfloat16(v.x - __bfloat162float(h0));
    __nv_bfloat16 l1 = __float2bfloat16(v.y - __bfloat162float(h1));
    __nv_bfloat16 l2 = __float2bfloat16(v.z - __bfloat162float(h2));
    __nv_bfloat16 l3 = __float2bfloat16(v.w - __bfloat162float(h3));
    __nv_bfloat162 hp0 = __nv_bfloat162(h0, h1);
    __nv_bfloat162 hp1 = __nv_bfloat162(h2, h3);
    __nv_bfloat162 lp0 = __nv_bfloat162(l0, l1);
    __nv_bfloat162 lp1 = __nv_bfloat162(l2, l3);
    hv.x = *(uint32_t*)&hp0; hv.y = *(uint32_t*)&hp1;
    lv.x = *(uint32_t*)&lp0; lv.y = *(uint32_t*)&lp1;
}

__global__ void split_kernel(const float* __restrict__ src,
                             __nv_bfloat16* __restrict__ hi,
                             __nv_bfloat16* __restrict__ lo, int n4)
{
    int i = blockIdx.x * blockDim.x + threadIdx.x;
    if (i >= n4) return;
    float4 v = ((const float4*)src)[i];
    uint2 hv, lv;
    split4(v, hv, lv);
    ((uint2*)hi)[i] = hv;
    ((uint2*)lo)[i] = lv;
}

// fp32 -> single fp16 conversion (for Wo)
__global__ void cvt_h_kernel(const float* __restrict__ src,
                             __half* __restrict__ dst, int n4)
{
    int i = blockIdx.x * blockDim.x + threadIdx.x;
    if (i >= n4) return;
    float4 v = ((const float4*)src)[i];
    __half2 p0 = __halves2half2(__float2half(v.x), __float2half(v.y));
    __half2 p1 = __halves2half2(__float2half(v.z), __float2half(v.w));
    uint2 o;
    o.x = *(uint32_t*)&p0; o.y = *(uint32_t*)&p1;
    ((uint2*)dst)[i] = o;
}

// ---------------------------------------------------------------------------
// MMA helpers
// ---------------------------------------------------------------------------
__device__ __forceinline__ uint32_t smem_u32(const void* p) {
    return (uint32_t)__cvta_generic_to_shared(p);
}
__device__ __forceinline__ void ldsm_x4(uint32_t* r, uint32_t addr) {
    asm volatile("ldmatrix.sync.aligned.m8n8.x4.shared.b16 {%0,%1,%2,%3}, [%4];"
        : "=r"(r[0]), "=r"(r[1]), "=r"(r[2]), "=r"(r[3]) : "r"(addr));
}
__device__ __forceinline__ void ldsm_x4_t(uint32_t* r, uint32_t addr) {
    asm volatile("ldmatrix.sync.aligned.m8n8.x4.trans.shared.b16 {%0,%1,%2,%3}, [%4];"
        : "=r"(r[0]), "=r"(r[1]), "=r"(r[2]), "=r"(r[3]) : "r"(addr));
}
__device__ __forceinline__ void mma_bf16(float* d, const uint32_t* a, const uint32_t* b) {
    asm volatile(
        "mma.sync.aligned.m16n8k16.row.col.f32.bf16.bf16.f32 "
        "{%0,%1,%2,%3}, {%4,%5,%6,%7}, {%8,%9}, {%0,%1,%2,%3};"
        : "+f"(d[0]), "+f"(d[1]), "+f"(d[2]), "+f"(d[3])
        : "r"(a[0]), "r"(a[1]), "r"(a[2]), "r"(a[3]), "r"(b[0]), "r"(b[1]));
}
__device__ __forceinline__ void mma_fp16(float* d, const uint32_t* a, const uint32_t* b) {
    asm volatile(
        "mma.sync.aligned.m16n8k16.row.col.f32.f16.f16.f32 "
        "{%0,%1,%2,%3}, {%4,%5,%6,%7}, {%8,%9}, {%0,%1,%2,%3};"
        : "+f"(d[0]), "+f"(d[1]), "+f"(d[2]), "+f"(d[3])
        : "r"(a[0]), "r"(a[1]), "r"(a[2]), "r"(a[3]), "r"(b[0]), "r"(b[1]));
}
__device__ __forceinline__ void cp16(uint32_t dst, const void* src) {
    asm volatile("cp.async.cg.shared.global [%0], [%1], 16;"
        :: "r"(dst), "l"(src));
}

// ---------------------------------------------------------------------------
// GEMM1: 3-pass split-bf16, 3-stage cp.async pipeline, 2 CTAs/SM.
// C[M,N] = (Ahi+Alo)(Bhi+Blo), dropping lo*lo.  A [M][K], B [K][N] row-major.
// Block tile 128 x 64 x 32; 4 warps, warp tile 64x32.
// ---------------------------------------------------------------------------
extern __shared__ char dsm[];

__global__ __launch_bounds__(128, 2) void gemm3p_kernel(
    const __nv_bfloat16* __restrict__ Ahi, const __nv_bfloat16* __restrict__ Alo,
    const __nv_bfloat16* __restrict__ Bhi, const __nv_bfloat16* __restrict__ Blo,
    float* __restrict__ C, int M, int N, int K)
{
    constexpr int TN_  = 64;
    constexpr int NT   = 128;
    constexpr int SKB_ = 72;
    constexpr uint32_t OFF_ALO = 10240;
    constexpr uint32_t OFF_BHI = 20480;
    constexpr uint32_t OFF_BLO = 20480u + 32u * SKB_ * 2u;
    constexpr uint32_t STG     = 20480u + 64u * SKB_ * 2u;   // 29696
    constexpr int BGRAN = 32 * (TN_ / 8);

    const int tid  = threadIdx.x;
    const int wid  = tid >> 5;
    const int lane = tid & 31;
    const int m0 = blockIdx.y * 128;
    const int n0 = blockIdx.x * TN_;

    const int wm = (wid & 1) * 64;
    const int wn = (wid >> 1) * 32;

    const uint32_t sb = smem_u32(dsm);

    float acc[4][4][4];
    #pragma unroll
    for (int i = 0; i < 4; i++)
        #pragma unroll
        for (int j = 0; j < 4; j++)
            #pragma unroll
            for (int k = 0; k < 4; k++) acc[i][j][k] = 0.0f;

    const int nk = K / 32;

    auto issue = [&](int slot, int kc) {
        const uint32_t s = sb + (uint32_t)slot * STG;
        #pragma unroll 2
        for (int i = tid; i < 512; i += NT) {
            int r = i >> 2, c = i & 3;
            uint32_t off = (uint32_t)(r * 80 + c * 16);
            size_t g = (size_t)(m0 + r) * K + (size_t)kc * 32 + c * 8;
            cp16(s + off, Ahi + g);
            cp16(s + OFF_ALO + off, Alo + g);
        }
        #pragma unroll 2
        for (int i = tid; i < BGRAN; i += NT) {
            int r = i / (TN_ / 8), c = i % (TN_ / 8);
            uint32_t off = (uint32_t)(r * (SKB_ * 2) + c * 16);
            size_t g = (size_t)(kc * 32 + r) * N + n0 + c * 8;
            cp16(s + OFF_BHI + off, Bhi + g);
            cp16(s + OFF_BLO + off, Blo + g);
        }
    };

    issue(0, 0);
    asm volatile("cp.async.commit_group;");
    if (nk > 1) issue(1, 1);
    asm volatile("cp.async.commit_group;");

    const int lm_row = lane & 15;
    const int lm_kch = (lane >> 4) * 8;

    int slot = 0;
    for (int kt = 0; kt < nk; kt++) {
        if (kt + 2 < nk) {
            int ps = slot + 2; if (ps >= 3) ps -= 3;
            issue(ps, kt + 2);
        }
        asm volatile("cp.async.commit_group;");
        asm volatile("cp.async.wait_group 2;");
        __syncthreads();

        const uint32_t stg = sb + (uint32_t)slot * STG;

        #pragma unroll
        for (int ks = 0; ks < 2; ks++) {
            const int k0 = ks * 16;
            uint32_t ah[4][4], al[4][4], bh[2][4], bl[2][4];
            #pragma unroll
            for (int mi = 0; mi < 4; mi++) {
                uint32_t off = (uint32_t)((wm + mi * 16 + lm_row) * 80
                                          + (k0 + lm_kch) * 2);
                ldsm_x4(ah[mi], stg + off);
                ldsm_x4(al[mi], stg + OFF_ALO + off);
            }
            #pragma unroll
            for (int np = 0; np < 2; np++) {
                uint32_t off = (uint32_t)((k0 + lm_row) * (SKB_ * 2)
                                          + (wn + np * 16 + lm_kch) * 2);
                ldsm_x4_t(bh[np], stg + OFF_BHI + off);
                ldsm_x4_t(bl[np], stg + OFF_BLO + off);
            }
            #pragma unroll
            for (int mi = 0; mi < 4; mi++) {
                #pragma unroll
                for (int nj = 0; nj < 4; nj++) {
                    const uint32_t* bhp = &bh[nj >> 1][(nj & 1) * 2];
                    const uint32_t* blp = &bl[nj >> 1][(nj & 1) * 2];
                    mma_bf16(acc[mi][nj], ah[mi], bhp);
                    mma_bf16(acc[mi][nj], ah[mi], blp);
                    mma_bf16(acc[mi][nj], al[mi], bhp);
                }
            }
        }
        __syncthreads();
        slot++; if (slot >= 3) slot = 0;
    }

    const int er = lane >> 2;
    const int ec = (lane & 3) * 2;
    #pragma unroll
    for (int mi = 0; mi < 4; mi++) {
        #pragma unroll
        for (int nj = 0; nj < 4; nj++) {
            const int row = m0 + wm + mi * 16 + er;
            const int col = n0 + wn + nj * 8 + ec;
            float2 v01; v01.x = acc[mi][nj][0]; v01.y = acc[mi][nj][1];
            float2 v23; v23.x = acc[mi][nj][2]; v23.y = acc[mi][nj][3];
            *(float2*)&C[(size_t)row * N + col]       = v01;
            *(float2*)&C[(size_t)(row + 8) * N + col] = v23;
        }
    }
}
#define SMEM_G1 (3 * 29696)   // 89088

// ---------------------------------------------------------------------------
// GEMM2: 2-pass fp16 (A split hi/lo, B single fp16), 3-stage pipeline.
// C[M,N] = (Ahi+Alo) @ B.  Block tile 128 x 96 x 32; 6 warps (192 thr).
// ---------------------------------------------------------------------------
__global__ __launch_bounds__(192, 2) void gemm2p_kernel(
    const __half* __restrict__ Ahi, const __half* __restrict__ Alo,
    const __half* __restrict__ B,
    float* __restrict__ C, int M, int N, int K)
{
    constexpr int TN_  = 96;
    constexpr int NT   = 192;
    constexpr int SKB_ = 104;
    constexpr uint32_t OFF_ALO = 10240;
    constexpr uint32_t OFF_B   = 20480;
    constexpr uint32_t STG     = 20480u + 32u * SKB_ * 2u;   // 27136
    constexpr int BGRAN = 32 * (TN_ / 8);   // 384

    const int tid  = threadIdx.x;
    const int wid  = tid >> 5;
    const int lane = tid & 31;
    const int m0 = blockIdx.y * 128;
    const int n0 = blockIdx.x * TN_;

    const int wm = (wid & 1) * 64;
    const int wn = (wid >> 1) * 32;

    const uint32_t sb = smem_u32(dsm);

    float acc[4][4][4];
    #pragma unroll
    for (int i = 0; i < 4; i++)
        #pragma unroll
        for (int j = 0; j < 4; j++)
            #pragma unroll
            for (int k = 0; k < 4; k++) acc[i][j][k] = 0.0f;

    const int nk = K / 32;

    auto issue = [&](int slot, int kc) {
        const uint32_t s = sb + (uint32_t)slot * STG;
        #pragma unroll 2
        for (int i = tid; i < 512; i += NT) {
            int r = i >> 2, c = i & 3;
            uint32_t off = (uint32_t)(r * 80 + c * 16);
            size_t g = (size_t)(m0 + r) * K + (size_t)kc * 32 + c * 8;
            cp16(s + off, Ahi + g);
            cp16(s + OFF_ALO + off, Alo + g);
        }
        #pragma unroll 2
        for (int i = tid; i < BGRAN; i += NT) {
            int r = i / (TN_ / 8), c = i % (TN_ / 8);
            uint32_t off = (uint32_t)(r * (SKB_ * 2) + c * 16);
            size_t g = (size_t)(kc * 32 + r) * N + n0 + c * 8;
            cp16(s + OFF_B + off, B + g);
        }
    };

    issue(0, 0);
    asm volatile("cp.async.commit_group;");
    if (nk > 1) issue(1, 1);
    asm volatile("cp.async.commit_group;");

    const int lm_row = lane & 15;
    const int lm_kch = (lane >> 4) * 8;

    int slot = 0;
    for (int kt = 0; kt < nk; kt++) {
        if (kt + 2 < nk) {
            int ps = slot + 2; if (ps >= 3) ps -= 3;
            issue(ps, kt + 2);
        }
        asm volatile("cp.async.commit_group;");
        asm volatile("cp.async.wait_group 2;");
        __syncthreads();

        const uint32_t stg = sb + (uint32_t)slot * STG;

        #pragma unroll
        for (int ks = 0; ks < 2; ks++) {
            const int k0 = ks * 16;
            uint32_t ah[4][4], al[4][4], bb[2][4];
            #pragma unroll
            for (int mi = 0; mi < 4; mi++) {
                uint32_t off = (uint32_t)((wm + mi * 16 + lm_row) * 80
                                          + (k0 + lm_kch) * 2);
                ldsm_x4(ah[mi], stg + off);
                ldsm_x4(al[mi], stg + OFF_ALO + off);
            }
            #pragma unroll
            for (int np = 0; np < 2; np++) {
                uint32_t off = (uint32_t)((k0 + lm_row) * (SKB_ * 2)
                                          + (wn + np * 16 + lm_kch) * 2);
                ldsm_x4_t(bb[np], stg + OFF_B + off);
            }
            #pragma unroll
            for (int mi = 0; mi < 4; mi++) {
                #pragma unroll
                for (int nj = 0; nj < 4; nj++) {
                    const uint32_t* bp = &bb[nj >> 1][(nj & 1) * 2];
                    mma_fp16(acc[mi][nj], ah[mi], bp);
                    mma_fp16(acc[mi][nj], al[mi], bp);
                }
            }
        }
        __syncthreads();
        slot++; if (slot >= 3) slot = 0;
    }

    const int er = lane >> 2;
    const int ec = (lane & 3) * 2;
    #pragma unroll
    for (int mi = 0; mi < 4; mi++) {
        #pragma unroll
        for (int nj = 0; nj < 4; nj++) {
            const int row = m0 + wm + mi * 16 + er;
            const int col = n0 + wn + nj * 8 + ec;
            float2 v01; v01.x = acc[mi][nj][0]; v01.y = acc[mi][nj][1];
            float2 v23; v23.x = acc[mi][nj][2]; v23.y = acc[mi][nj][3];
            *(float2*)&C[(size_t)row * N + col]       = v01;
            *(float2*)&C[(size_t)(row + 8) * N + col] = v23;
        }
    }
}
#define SMEM_G2 (3 * 27136)   // 81408

// ---------------------------------------------------------------------------
// RoPE in-place on qkv (q: 64 heads, k: 8 heads).
// ---------------------------------------------------------------------------
__global__ void rope_kernel(float* __restrict__ qkv, int n)
{
    int idx = blockIdx.x * blockDim.x + threadIdx.x;
    int total = n * (NHEADS + NKV) * (DHEAD / 2);
    if (idx >= total) return;

    int j   = idx & 31;
    int h   = (idx >> 5) % (NHEADS + NKV);
    int tok = idx / ((NHEADS + NKV) * 32);

    float* base;
    if (h < NHEADS)
        base = qkv + (size_t)tok * QKVW + h * DHEAD;
    else
        base = qkv + (size_t)tok * QKVW + NHEADS * DHEAD + (h - NHEADS) * DHEAD;

    float pos = (float)g_positions[tok];
    float inv_freq = powf(150000.0f, -((float)j) / 32.0f);
    float ang = pos * inv_freq;
    float s, c;
    sincosf(ang, &s, &c);

    float x1 = base[j];
    float x2 = base[j + 32];
    base[j]      = x1 * c - x2 * s;
    base[j + 32] = x2 * c + x1 * s;
}

// ---------------------------------------------------------------------------
// Sliding-window attention with sinks, 2 tokens per block.
// Grid: (n/2, NKV). Block: 256 threads. Writes fp16 hi/lo split directly.
// ---------------------------------------------------------------------------
#define UNI 129

__global__ __launch_bounds__(256) void attn_kernel(
    const float* __restrict__ qkv, const float* __restrict__ sinks,
    __half* __restrict__ out_hi, __half* __restrict__ out_lo,
    int n)
{
    __shared__ float kbuf[UNI + 1][68];    // K then V
    __shared__ float qs[2][GRP][DHEAD];    // scaled q
    __shared__ float sc[2][GRP][132];      // scores -> probs (index u)
    __shared__ float dinv[2][GRP];

    const int tok0 = blockIdx.x * 2;
    const int kv   = blockIdx.y;
    const int tid  = threadIdx.x;
    const int lane = tid & 31;
    const int wid  = tid >> 5;

    const int p0 = g_positions[tok0];

    for (int i = tid; i < 2 * GRP * DHEAD; i += 256) {
        int j = i >> 9, r = i & 511;
        qs[j][r >> 6][r & 63] =
            qkv[(size_t)(tok0 + j) * QKVW + (size_t)kv * GRP * DHEAD + r] * 0.125f;
    }

    for (int i = tid; i < UNI * (DHEAD / 4); i += 256) {
        int u  = i >> 4;
        int c4 = (i & 15) << 2;
        int t = p0 - (WIN - 1) + u;
        t = max(0, min(t, n - 1));
        float4 kd = *(const float4*)(qkv + (size_t)t * QKVW + NHEADS * DHEAD
                                     + (size_t)kv * DHEAD + c4);
        *(float4*)&kbuf[u][c4] = kd;
    }
    __syncthreads();

    if (tid < UNI) {
        const int u = tid;
        float s[2][GRP];
        #pragma unroll
        for (int j = 0; j < 2; j++)
            #pragma unroll
            for (int g = 0; g < GRP; g++) s[j][g] = 0.0f;

        #pragma unroll 4
        for (int d4 = 0; d4 < DHEAD / 4; d4++) {
            float4 kd = *(const float4*)&kbuf[u][d4 * 4];
            #pragma unroll
            for (int j = 0; j < 2; j++)
                #pragma unroll
                for (int g = 0; g < GRP; g++) {
                    s[j][g] += kd.x * qs[j][g][d4 * 4 + 0];
                    s[j][g] += kd.y * qs[j][g][d4 * 4 + 1];
                    s[j][g] += kd.z * qs[j][g][d4 * 4 + 2];
                    s[j][g] += kd.w * qs[j][g][d4 * 4 + 3];
                }
        }

        const bool tvalid = (p0 - (WIN - 1) + u) >= 0;
        #pragma unroll
        for (int j = 0; j < 2; j++) {
            int w = u - j;
            bool inw = (w >= 0) && (w < WIN);
            #pragma unroll
            for (int g = 0; g < GRP; g++)
                sc[j][g][u] = inw ? (tvalid ? s[j][g] : -INFINITY) : 0.0f;
        }
    }
    __syncthreads();

    #pragma unroll
    for (int pp = 0; pp < 2; pp++) {
        int p = wid * 2 + pp;
        int j = p >> 3, g = p & 7;
        float vals[4];
        #pragma unroll
        for (int i = 0; i < 4; i++)
            vals[i] = sc[j][g][j + lane + i * 32];
        float m = fmaxf(fmaxf(vals[0], vals[1]), fmaxf(vals[2], vals[3]));
        #pragma unroll
        for (int off = 16; off; off >>= 1)
            m = fmaxf(m, __shfl_xor_sync(0xffffffffu, m, off));
        float snk = sinks[kv * GRP + g];
        m = fmaxf(m, snk);
        float ssum = 0.0f;
        #pragma unroll
        for (int i = 0; i < 4; i++) {
            float pv = expf(vals[i] - m);
            sc[j][g][j + lane + i * 32] = pv;
            ssum += pv;
        }
        #pragma unroll
        for (int off = 16; off; off >>= 1)
            ssum += __shfl_xor_sync(0xffffffffu, ssum, off);
        if (lane == 0)
            dinv[j][g] = 1.0f / (ssum + expf(snk - m));
    }

    for (int i = tid; i < UNI * (DHEAD / 4); i += 256) {
        int u  = i >> 4;
        int c4 = (i & 15) << 2;
        int t = p0 - (WIN - 1) + u;
        t = max(0, min(t, n - 1));
        float4 vd = *(const float4*)(qkv + (size_t)t * QKVW
                                     + (NHEADS + NKV) * DHEAD
                                     + (size_t)kv * DHEAD + c4);
        *(float4*)&kbuf[u][c4] = vd;
    }
    __syncthreads();

    {
        const int g  = tid >> 5;
        const int d2 = (tid & 31) * 2;
        float a00 = 0.f, a01 = 0.f, a10 = 0.f, a11 = 0.f;
        #pragma unroll 4
        for (int u = 0; u < UNI; u++) {
            float2 vd = *(const float2*)&kbuf[u][d2];
            float p0j = sc[0][g][u];
            float p1j = sc[1][g][u];
            a00 += p0j * vd.x; a01 += p0j * vd.y;
            a10 += p1j * vd.x; a11 += p1j * vd.y;
        }
        float di0 = dinv[0][g], di1 = dinv[1][g];
        float o00 = a00 * di0, o01 = a01 * di0;
        float o10 = a10 * di1, o11 = a11 * di1;

        size_t base0 = (size_t)tok0 * AOW + ((size_t)kv * GRP + g) * DHEAD + d2;
        size_t base1 = base0 + AOW;
        __half h;
        h = __float2half(o00); out_hi[base0]   = h; out_lo[base0]   = __float2half(o00 - __half2float(h));
        h = __float2half(o01); out_hi[base0+1] = h; out_lo[base0+1] = __float2half(o01 - __half2float(h));
        h = __float2half(o10); out_hi[base1]   = h; out_lo[base1]   = __float2half(o10 - __half2float(h));
        h = __float2half(o11); out_hi[base1+1] = h; out_lo[base1+1] = __float2half(o11 - __half2float(h));
    }
}

// ---------------------------------------------------------------------------
extern "C" void kernel_launch(void* const* d_in, const int* in_sizes, int n_in,
                              void* d_out, int out_size)
{
    const float* hs    = (const float*)d_in[0];
    const float* wqkv  = (const float*)d_in[1];
    const float* wo    = (const float*)d_in[2];
    const float* sinks = (const float*)d_in[3];
    const void*  pos   = (const void*)d_in[4];
    float*       out   = (float*)d_out;

    const int n = in_sizes[0] / HDIM;   // 1024

    float* qkv_ptr;
    __nv_bfloat16 *ahi, *alo, *wqh, *wql;
    __half *athi, *atlo, *woh;
    cudaGetSymbolAddress((void**)&qkv_ptr,  g_qkv);
    cudaGetSymbolAddress((void**)&ahi,  g_ahi);
    cudaGetSymbolAddress((void**)&alo,  g_alo);
    cudaGetSymbolAddress((void**)&athi, g_athi);
    cudaGetSymbolAddress((void**)&atlo, g_atlo);
    cudaGetSymbolAddress((void**)&wqh,  g_wqh);
    cudaGetSymbolAddress((void**)&wql,  g_wql);
    cudaGetSymbolAddress((void**)&woh,  g_woh);

    cudaFuncSetAttribute(gemm3p_kernel,
                         cudaFuncAttributeMaxDynamicSharedMemorySize, SMEM_G1);
    cudaFuncSetAttribute(gemm2p_kernel,
                         cudaFuncAttributeMaxDynamicSharedMemorySize, SMEM_G2);

    // 0) normalize positions
    norm_pos_kernel<<<1, 1024>>>(pos, n);

    // 1) conversions: hs + Wqkv bf16 hi/lo split; Wo single fp16
    {
        int n4 = (n * HDIM) / 4;
        split_kernel<<<(n4 + 255) / 256, 256>>>(hs, ahi, alo, n4);
        n4 = (HDIM * QKVW) / 4;
        split_kernel<<<(n4 + 255) / 256, 256>>>(wqkv, wqh, wql, n4);
        n4 = (AOW * HDIM) / 4;
        cvt_h_kernel<<<(n4 + 255) / 256, 256>>>(wo, woh, n4);
    }

    // 2) qkv = hs @ Wqkv   (bf16 3-pass, N tile 64: 5120 = 80*64)
    {
        dim3 grid(QKVW / 64, n / 128);
        gemm3p_kernel<<<grid, 128, SMEM_G1>>>(ahi, alo, wqh, wql, qkv_ptr,
                                              n, QKVW, HDIM);
    }

    // 3) RoPE in place on q and k
    {
        int total = n * (NHEADS + NKV) * (DHEAD / 2);
        rope_kernel<<<(total + 255) / 256, 256>>>(qkv_ptr, n);
    }

    // 4) attention (2 tokens/block), writes fp16 hi/lo directly
    {
        dim3 grid(n / 2, NKV);
        attn_kernel<<<grid, 256>>>(qkv_ptr, sinks, athi, atlo, n);
    }

    // 5) out = attn @ Wo   (fp16 2-pass, N tile 96: 2880 = 30*96, single wave)
    {
        dim3 grid(HDIM / 96, n / 128);
        gemm2p_kernel<<<grid, 192, SMEM_G2>>>(athi, atlo, woh, out,
                                              n, HDIM, AOW);
    }
}

// round 9
// speedup vs baseline: 1.7344x; 1.3153x over previous
#include <cuda_runtime.h>
#include <cuda_bf16.h>
#include <cuda_fp16.h>
#include <math.h>
#include <stdint.h>

// Problem constants
#define HDIM   2880
#define NHEADS 64
#define NKV    8
#define DHEAD  64
#define GRP    8          // NHEADS / NKV
#define WIN    128
#define QKVW   5120       // (NHEADS + 2*NKV) * DHEAD
#define AOW    4096       // NHEADS * DHEAD
#define NMAX   1024

// Scratch (device globals: allocation-free)
__device__ float g_qkv[NMAX * QKVW];   // 20 MB
__device__ int   g_positions[NMAX];

__device__ __align__(16) __half g_ahi[NMAX * HDIM];
__device__ __align__(16) __half g_alo[NMAX * HDIM];
__device__ __align__(16) __half g_athi[NMAX * AOW];
__device__ __align__(16) __half g_atlo[NMAX * AOW];
__device__ __align__(16) __half g_wq[HDIM * QKVW];    // single fp16 Wqkv
__device__ __align__(16) __half g_wo[AOW * HDIM];     // single fp16 Wo

// ---------------------------------------------------------------------------
// positions normalizer (int32 vs int64 robust; positions are arange here)
// ---------------------------------------------------------------------------
__global__ void norm_pos_kernel(const void* __restrict__ pos_raw, int n)
{
    const long long* p64 = (const long long*)pos_raw;
    const int*       p32 = (const int*)pos_raw;
    __shared__ int is64;
    if (threadIdx.x == 0) {
        long long v0 = p64[0];
        long long v1 = (n > 1) ? p64[1] : 1;
        is64 = (v0 == 0 && v1 == 1) ? 1 : 0;
    }
    __syncthreads();
    for (int i = threadIdx.x; i < n; i += blockDim.x)
        g_positions[i] = is64 ? (int)p64[i] : p32[i];
}

// ---------------------------------------------------------------------------
// fp32 -> fp16 hi/lo split (vectorized x4)
// ---------------------------------------------------------------------------
__global__ void splith_kernel(const float* __restrict__ src,
                              __half* __restrict__ hi,
                              __half* __restrict__ lo, int n4)
{
    int i = blockIdx.x * blockDim.x + threadIdx.x;
    if (i >= n4) return;
    float4 v = ((const float4*)src)[i];
    __half h0 = __float2half(v.x);
    __half h1 = __float2half(v.y);
    __half h2 = __float2half(v.z);
    __half h3 = __float2half(v.w);
    __half l0 = __float2half(v.x - __half2float(h0));
    __half l1 = __float2half(v.y - __half2float(h1));
    __half l2 = __float2half(v.z - __half2float(h2));
    __half l3 = __float2half(v.w - __half2float(h3));
    __half2 hp0 = __halves2half2(h0, h1), hp1 = __halves2half2(h2, h3);
    __half2 lp0 = __halves2half2(l0, l1), lp1 = __halves2half2(l2, l3);
    uint2 hv, lv;
    hv.x = *(uint32_t*)&hp0; hv.y = *(uint32_t*)&hp1;
    lv.x = *(uint32_t*)&lp0; lv.y = *(uint32_t*)&lp1;
    ((uint2*)hi)[i] = hv;
    ((uint2*)lo)[i] = lv;
}

// fp32 -> single fp16 conversion (weights)
__global__ void cvt_h_kernel(const float* __restrict__ src,
                             __half* __restrict__ dst, int n4)
{
    int i = blockIdx.x * blockDim.x + threadIdx.x;
    if (i >= n4) return;
    float4 v = ((const float4*)src)[i];
    __half2 p0 = __halves2half2(__float2half(v.x), __float2half(v.y));
    __half2 p1 = __halves2half2(__float2half(v.z), __float2half(v.w));
    uint2 o;
    o.x = *(uint32_t*)&p0; o.y = *(uint32_t*)&p1;
    ((uint2*)dst)[i] = o;
}

// ---------------------------------------------------------------------------
// MMA helpers
// ---------------------------------------------------------------------------
__device__ __forceinline__ uint32_t smem_u32(const void* p) {
    return (uint32_t)__cvta_generic_to_shared(p);
}
__device__ __forceinline__ void ldsm_x4(uint32_t* r, uint32_t addr) {
    asm volatile("ldmatrix.sync.aligned.m8n8.x4.shared.b16 {%0,%1,%2,%3}, [%4];"
        : "=r"(r[0]), "=r"(r[1]), "=r"(r[2]), "=r"(r[3]) : "r"(addr));
}
__device__ __forceinline__ void ldsm_x4_t(uint32_t* r, uint32_t addr) {
    asm volatile("ldmatrix.sync.aligned.m8n8.x4.trans.shared.b16 {%0,%1,%2,%3}, [%4];"
        : "=r"(r[0]), "=r"(r[1]), "=r"(r[2]), "=r"(r[3]) : "r"(addr));
}
__device__ __forceinline__ void mma_fp16(float* d, const uint32_t* a, const uint32_t* b) {
    asm volatile(
        "mma.sync.aligned.m16n8k16.row.col.f32.f16.f16.f32 "
        "{%0,%1,%2,%3}, {%4,%5,%6,%7}, {%8,%9}, {%0,%1,%2,%3};"
        : "+f"(d[0]), "+f"(d[1]), "+f"(d[2]), "+f"(d[3])
        : "r"(a[0]), "r"(a[1]), "r"(a[2]), "r"(a[3]), "r"(b[0]), "r"(b[1]));
}
__device__ __forceinline__ void cp16(uint32_t dst, const void* src) {
    asm volatile("cp.async.cg.shared.global [%0], [%1], 16;"
        :: "r"(dst), "l"(src));
}

// ---------------------------------------------------------------------------
// 2-pass fp16 GEMM (A split hi/lo, B single fp16), 3-stage cp.async pipeline,
// 2 CTAs/SM.  C[M,N] = (Ahi+Alo) @ B.  A [M][K], B [K][N] row-major.
// Block tile 128 x TN_ x 32; warps 2 x (TN_/32), warp tile 64x32.
// Requires M%128==0, N%TN_==0, K%32==0.
// ---------------------------------------------------------------------------
extern __shared__ char dsm[];

template<int TN_>
__global__ __launch_bounds__(TN_ * 2, 2) void gemm2p_kernel(
    const __half* __restrict__ Ahi, const __half* __restrict__ Alo,
    const __half* __restrict__ B,
    float* __restrict__ C, int M, int N, int K)
{
    constexpr int NT   = TN_ * 2;
    constexpr int SKB_ = TN_ + 8;
    constexpr uint32_t OFF_ALO = 10240;
    constexpr uint32_t OFF_B   = 20480;
    constexpr uint32_t STG     = 20480u + 32u * SKB_ * 2u;
    constexpr int BGRAN = 32 * (TN_ / 8);

    const int tid  = threadIdx.x;
    const int wid  = tid >> 5;
    const int lane = tid & 31;
    const int m0 = blockIdx.y * 128;
    const int n0 = blockIdx.x * TN_;

    const int wm = (wid & 1) * 64;
    const int wn = (wid >> 1) * 32;

    const uint32_t sb = smem_u32(dsm);

    float acc[4][4][4];
    #pragma unroll
    for (int i = 0; i < 4; i++)
        #pragma unroll
        for (int j = 0; j < 4; j++)
            #pragma unroll
            for (int k = 0; k < 4; k++) acc[i][j][k] = 0.0f;

    const int nk = K / 32;

    auto issue = [&](int slot, int kc) {
        const uint32_t s = sb + (uint32_t)slot * STG;
        #pragma unroll 2
        for (int i = tid; i < 512; i += NT) {          // A: 128 rows x 4 granules
            int r = i >> 2, c = i & 3;
            uint32_t off = (uint32_t)(r * 80 + c * 16);
            size_t g = (size_t)(m0 + r) * K + (size_t)kc * 32 + c * 8;
            cp16(s + off, Ahi + g);
            cp16(s + OFF_ALO + off, Alo + g);
        }
        #pragma unroll 2
        for (int i = tid; i < BGRAN; i += NT) {        // B: 32 rows x TN_/8 granules
            int r = i / (TN_ / 8), c = i % (TN_ / 8);
            uint32_t off = (uint32_t)(r * (SKB_ * 2) + c * 16);
            size_t g = (size_t)(kc * 32 + r) * N + n0 + c * 8;
            cp16(s + OFF_B + off, B + g);
        }
    };

    issue(0, 0);
    asm volatile("cp.async.commit_group;");
    if (nk > 1) issue(1, 1);
    asm volatile("cp.async.commit_group;");

    const int lm_row = lane & 15;
    const int lm_kch = (lane >> 4) * 8;

    int slot = 0;
    for (int kt = 0; kt < nk; kt++) {
        if (kt + 2 < nk) {
            int ps = slot + 2; if (ps >= 3) ps -= 3;
            issue(ps, kt + 2);
        }
        asm volatile("cp.async.commit_group;");
        asm volatile("cp.async.wait_group 2;");
        __syncthreads();

        const uint32_t stg = sb + (uint32_t)slot * STG;

        #pragma unroll
        for (int ks = 0; ks < 2; ks++) {
            const int k0 = ks * 16;
            uint32_t ah[4][4], al[4][4], bb[2][4];
            #pragma unroll
            for (int mi = 0; mi < 4; mi++) {
                uint32_t off = (uint32_t)((wm + mi * 16 + lm_row) * 80
                                          + (k0 + lm_kch) * 2);
                ldsm_x4(ah[mi], stg + off);
                ldsm_x4(al[mi], stg + OFF_ALO + off);
            }
            #pragma unroll
            for (int np = 0; np < 2; np++) {
                uint32_t off = (uint32_t)((k0 + lm_row) * (SKB_ * 2)
                                          + (wn + np * 16 + lm_kch) * 2);
                ldsm_x4_t(bb[np], stg + OFF_B + off);
            }
            #pragma unroll
            for (int mi = 0; mi < 4; mi++) {
                #pragma unroll
                for (int nj = 0; nj < 4; nj++) {
                    const uint32_t* bp = &bb[nj >> 1][(nj & 1) * 2];
                    mma_fp16(acc[mi][nj], ah[mi], bp);
                    mma_fp16(acc[mi][nj], al[mi], bp);
                }
            }
        }
        __syncthreads();
        slot++; if (slot >= 3) slot = 0;
    }

    const int er = lane >> 2;
    const int ec = (lane & 3) * 2;
    #pragma unroll
    for (int mi = 0; mi < 4; mi++) {
        #pragma unroll
        for (int nj = 0; nj < 4; nj++) {
            const int row = m0 + wm + mi * 16 + er;
            const int col = n0 + wn + nj * 8 + ec;
            float2 v01; v01.x = acc[mi][nj][0]; v01.y = acc[mi][nj][1];
            float2 v23; v23.x = acc[mi][nj][2]; v23.y = acc[mi][nj][3];
            *(float2*)&C[(size_t)row * N + col]       = v01;
            *(float2*)&C[(size_t)(row + 8) * N + col] = v23;
        }
    }
}

#define SMEM_T64 (3 * (20480 + 32 * 72 * 2))    // 75264
#define SMEM_T96 (3 * (20480 + 32 * 104 * 2))   // 81408

// ---------------------------------------------------------------------------
// RoPE in-place on qkv (q: 64 heads, k: 8 heads).
// ---------------------------------------------------------------------------
__global__ void rope_kernel(float* __restrict__ qkv, int n)
{
    int idx = blockIdx.x * blockDim.x + threadIdx.x;
    int total = n * (NHEADS + NKV) * (DHEAD / 2);
    if (idx >= total) return;

    int j   = idx & 31;
    int h   = (idx >> 5) % (NHEADS + NKV);
    int tok = idx / ((NHEADS + NKV) * 32);

    float* base;
    if (h < NHEADS)
        base = qkv + (size_t)tok * QKVW + h * DHEAD;
    else
        base = qkv + (size_t)tok * QKVW + NHEADS * DHEAD + (h - NHEADS) * DHEAD;

    float pos = (float)g_positions[tok];
    float inv_freq = powf(150000.0f, -((float)j) / 32.0f);
    float ang = pos * inv_freq;
    float s, c;
    sincosf(ang, &s, &c);

    float x1 = base[j];
    float x2 = base[j + 32];
    base[j]      = x1 * c - x2 * s;
    base[j + 32] = x2 * c + x1 * s;
}

// ---------------------------------------------------------------------------
// Sliding-window attention with sinks, 2 tokens per block.
// Grid: (n/2, NKV). Block: 256 threads. Writes fp16 hi/lo split directly.
// ---------------------------------------------------------------------------
#define UNI 129

__global__ __launch_bounds__(256) void attn_kernel(
    const float* __restrict__ qkv, const float* __restrict__ sinks,
    __half* __restrict__ out_hi, __half* __restrict__ out_lo,
    int n)
{
    __shared__ float kbuf[UNI + 1][68];    // K then V
    __shared__ float qs[2][GRP][DHEAD];    // scaled q
    __shared__ float sc[2][GRP][132];      // scores -> probs (index u)
    __shared__ float dinv[2][GRP];

    const int tok0 = blockIdx.x * 2;
    const int kv   = blockIdx.y;
    const int tid  = threadIdx.x;
    const int lane = tid & 31;
    const int wid  = tid >> 5;

    const int p0 = g_positions[tok0];

    for (int i = tid; i < 2 * GRP * DHEAD; i += 256) {
        int j = i >> 9, r = i & 511;
        qs[j][r >> 6][r & 63] =
            qkv[(size_t)(tok0 + j) * QKVW + (size_t)kv * GRP * DHEAD + r] * 0.125f;
    }

    for (int i = tid; i < UNI * (DHEAD / 4); i += 256) {
        int u  = i >> 4;
        int c4 = (i & 15) << 2;
        int t = p0 - (WIN - 1) + u;
        t = max(0, min(t, n - 1));
        float4 kd = *(const float4*)(qkv + (size_t)t * QKVW + NHEADS * DHEAD
                                     + (size_t)kv * DHEAD + c4);
        *(float4*)&kbuf[u][c4] = kd;
    }
    __syncthreads();

    if (tid < UNI) {
        const int u = tid;
        float s[2][GRP];
        #pragma unroll
        for (int j = 0; j < 2; j++)
            #pragma unroll
            for (int g = 0; g < GRP; g++) s[j][g] = 0.0f;

        #pragma unroll 4
        for (int d4 = 0; d4 < DHEAD / 4; d4++) {
            float4 kd = *(const float4*)&kbuf[u][d4 * 4];
            #pragma unroll
            for (int j = 0; j < 2; j++)
                #pragma unroll
                for (int g = 0; g < GRP; g++) {
                    s[j][g] += kd.x * qs[j][g][d4 * 4 + 0];
                    s[j][g] += kd.y * qs[j][g][d4 * 4 + 1];
                    s[j][g] += kd.z * qs[j][g][d4 * 4 + 2];
                    s[j][g] += kd.w * qs[j][g][d4 * 4 + 3];
                }
        }

        const bool tvalid = (p0 - (WIN - 1) + u) >= 0;
        #pragma unroll
        for (int j = 0; j < 2; j++) {
            int w = u - j;
            bool inw = (w >= 0) && (w < WIN);
            #pragma unroll
            for (int g = 0; g < GRP; g++)
                sc[j][g][u] = inw ? (tvalid ? s[j][g] : -INFINITY) : 0.0f;
        }
    }
    __syncthreads();

    #pragma unroll
    for (int pp = 0; pp < 2; pp++) {
        int p = wid * 2 + pp;
        int j = p >> 3, g = p & 7;
        float vals[4];
        #pragma unroll
        for (int i = 0; i < 4; i++)
            vals[i] = sc[j][g][j + lane + i * 32];
        float m = fmaxf(fmaxf(vals[0], vals[1]), fmaxf(vals[2], vals[3]));
        #pragma unroll
        for (int off = 16; off; off >>= 1)
            m = fmaxf(m, __shfl_xor_sync(0xffffffffu, m, off));
        float snk = sinks[kv * GRP + g];
        m = fmaxf(m, snk);
        float ssum = 0.0f;
        #pragma unroll
        for (int i = 0; i < 4; i++) {
            float pv = expf(vals[i] - m);
            sc[j][g][j + lane + i * 32] = pv;
            ssum += pv;
        }
        #pragma unroll
        for (int off = 16; off; off >>= 1)
            ssum += __shfl_xor_sync(0xffffffffu, ssum, off);
        if (lane == 0)
            dinv[j][g] = 1.0f / (ssum + expf(snk - m));
    }

    for (int i = tid; i < UNI * (DHEAD / 4); i += 256) {
        int u  = i >> 4;
        int c4 = (i & 15) << 2;
        int t = p0 - (WIN - 1) + u;
        t = max(0, min(t, n - 1));
        float4 vd = *(const float4*)(qkv + (size_t)t * QKVW
                                     + (NHEADS + NKV) * DHEAD
                                     + (size_t)kv * DHEAD + c4);
        *(float4*)&kbuf[u][c4] = vd;
    }
    __syncthreads();

    {
        const int g  = tid >> 5;
        const int d2 = (tid & 31) * 2;
        float a00 = 0.f, a01 = 0.f, a10 = 0.f, a11 = 0.f;
        #pragma unroll 4
        for (int u = 0; u < UNI; u++) {
            float2 vd = *(const float2*)&kbuf[u][d2];
            float p0j = sc[0][g][u];
            float p1j = sc[1][g][u];
            a00 += p0j * vd.x; a01 += p0j * vd.y;
            a10 += p1j * vd.x; a11 += p1j * vd.y;
        }
        float di0 = dinv[0][g], di1 = dinv[1][g];
        float o00 = a00 * di0, o01 = a01 * di0;
        float o10 = a10 * di1, o11 = a11 * di1;

        size_t base0 = (size_t)tok0 * AOW + ((size_t)kv * GRP + g) * DHEAD + d2;
        size_t base1 = base0 + AOW;
        __half h;
        h = __float2half(o00); out_hi[base0]   = h; out_lo[base0]   = __float2half(o00 - __half2float(h));
        h = __float2half(o01); out_hi[base0+1] = h; out_lo[base0+1] = __float2half(o01 - __half2float(h));
        h = __float2half(o10); out_hi[base1]   = h; out_lo[base1]   = __float2half(o10 - __half2float(h));
        h = __float2half(o11); out_hi[base1+1] = h; out_lo[base1+1] = __float2half(o11 - __half2float(h));
    }
}

// ---------------------------------------------------------------------------
extern "C" void kernel_launch(void* const* d_in, const int* in_sizes, int n_in,
                              void* d_out, int out_size)
{
    const float* hs    = (const float*)d_in[0];
    const float* wqkv  = (const float*)d_in[1];
    const float* wo    = (const float*)d_in[2];
    const float* sinks = (const float*)d_in[3];
    const void*  pos   = (const void*)d_in[4];
    float*       out   = (float*)d_out;

    const int n = in_sizes[0] / HDIM;   // 1024

    float* qkv_ptr;
    __half *ahi, *alo, *athi, *atlo, *wq, *wo16;
    cudaGetSymbolAddress((void**)&qkv_ptr,  g_qkv);
    cudaGetSymbolAddress((void**)&ahi,  g_ahi);
    cudaGetSymbolAddress((void**)&alo,  g_alo);
    cudaGetSymbolAddress((void**)&athi, g_athi);
    cudaGetSymbolAddress((void**)&atlo, g_atlo);
    cudaGetSymbolAddress((void**)&wq,   g_wq);
    cudaGetSymbolAddress((void**)&wo16, g_wo);

    cudaFuncSetAttribute(gemm2p_kernel<64>,
                         cudaFuncAttributeMaxDynamicSharedMemorySize, SMEM_T64);
    cudaFuncSetAttribute(gemm2p_kernel<96>,
                         cudaFuncAttributeMaxDynamicSharedMemorySize, SMEM_T96);

    // 0) normalize positions
    norm_pos_kernel<<<1, 1024>>>(pos, n);

    // 1) conversions: hs fp16 hi/lo split; Wqkv + Wo single fp16
    {
        int n4 = (n * HDIM) / 4;
        splith_kernel<<<(n4 + 255) / 256, 256>>>(hs, ahi, alo, n4);
        n4 = (HDIM * QKVW) / 4;
        cvt_h_kernel<<<(n4 + 255) / 256, 256>>>(wqkv, wq, n4);
        n4 = (AOW * HDIM) / 4;
        cvt_h_kernel<<<(n4 + 255) / 256, 256>>>(wo, wo16, n4);
    }

    // 2) qkv = hs @ Wqkv   (fp16 2-pass, N tile 64: 5120 = 80*64)
    {
        dim3 grid(QKVW / 64, n / 128);
        gemm2p_kernel<64><<<grid, 128, SMEM_T64>>>(ahi, alo, wq, qkv_ptr,
                                                   n, QKVW, HDIM);
    }

    // 3) RoPE in place on q and k
    {
        int total = n * (NHEADS + NKV) * (DHEAD / 2);
        rope_kernel<<<(total + 255) / 256, 256>>>(qkv_ptr, n);
    }

    // 4) attention (2 tokens/block), writes fp16 hi/lo directly
    {
        dim3 grid(n / 2, NKV);
        attn_kernel<<<grid, 256>>>(qkv_ptr, sinks, athi, atlo, n);
    }

    // 5) out = attn @ Wo   (fp16 2-pass, N tile 96: 2880 = 30*96, single wave)
    {
        dim3 grid(HDIM / 96, n / 128);
        gemm2p_kernel<96><<<grid, 192, SMEM_T96>>>(athi, atlo, wo16, out,
                                                   n, HDIM, AOW);
    }
}

// round 10
// speedup vs baseline: 2.5267x; 1.4568x over previous
#include <cuda_runtime.h>
#include <cuda_fp16.h>
#include <math.h>
#include <stdint.h>

// Problem constants
#define HDIM   2880
#define NHEADS 64
#define NKV    8
#define DHEAD  64
#define GRP    8          // NHEADS / NKV
#define WIN    128
#define QKVW   5120       // (NHEADS + 2*NKV) * DHEAD
#define AOW    4096       // NHEADS * DHEAD
#define NMAX   1024

// Scratch (device globals: allocation-free)
__device__ float g_qkv[NMAX * QKVW];   // 20 MB
__device__ int   g_positions[NMAX];

__device__ __align__(16) __half g_ah[NMAX * HDIM];    // fp16 hidden states
__device__ __align__(16) __half g_ath[NMAX * AOW];    // fp16 attn output
__device__ __align__(16) __half g_wq[HDIM * QKVW];    // fp16 Wqkv
__device__ __align__(16) __half g_wo[AOW * HDIM];     // fp16 Wo

// ---------------------------------------------------------------------------
// positions normalizer (int32 vs int64 robust; positions are arange here)
// ---------------------------------------------------------------------------
__global__ void norm_pos_kernel(const void* __restrict__ pos_raw, int n)
{
    const long long* p64 = (const long long*)pos_raw;
    const int*       p32 = (const int*)pos_raw;
    __shared__ int is64;
    if (threadIdx.x == 0) {
        long long v0 = p64[0];
        long long v1 = (n > 1) ? p64[1] : 1;
        is64 = (v0 == 0 && v1 == 1) ? 1 : 0;
    }
    __syncthreads();
    for (int i = threadIdx.x; i < n; i += blockDim.x)
        g_positions[i] = is64 ? (int)p64[i] : p32[i];
}

// ---------------------------------------------------------------------------
// fp32 -> fp16 conversion (vectorized x4)
// ---------------------------------------------------------------------------
__global__ void cvt_h_kernel(const float* __restrict__ src,
                             __half* __restrict__ dst, int n4)
{
    int i = blockIdx.x * blockDim.x + threadIdx.x;
    if (i >= n4) return;
    float4 v = ((const float4*)src)[i];
    __half2 p0 = __halves2half2(__float2half(v.x), __float2half(v.y));
    __half2 p1 = __halves2half2(__float2half(v.z), __float2half(v.w));
    uint2 o;
    o.x = *(uint32_t*)&p0; o.y = *(uint32_t*)&p1;
    ((uint2*)dst)[i] = o;
}

// ---------------------------------------------------------------------------
// MMA helpers
// ---------------------------------------------------------------------------
__device__ __forceinline__ uint32_t smem_u32(const void* p) {
    return (uint32_t)__cvta_generic_to_shared(p);
}
__device__ __forceinline__ void ldsm_x4(uint32_t* r, uint32_t addr) {
    asm volatile("ldmatrix.sync.aligned.m8n8.x4.shared.b16 {%0,%1,%2,%3}, [%4];"
        : "=r"(r[0]), "=r"(r[1]), "=r"(r[2]), "=r"(r[3]) : "r"(addr));
}
__device__ __forceinline__ void ldsm_x4_t(uint32_t* r, uint32_t addr) {
    asm volatile("ldmatrix.sync.aligned.m8n8.x4.trans.shared.b16 {%0,%1,%2,%3}, [%4];"
        : "=r"(r[0]), "=r"(r[1]), "=r"(r[2]), "=r"(r[3]) : "r"(addr));
}
__device__ __forceinline__ void mma_fp16(float* d, const uint32_t* a, const uint32_t* b) {
    asm volatile(
        "mma.sync.aligned.m16n8k16.row.col.f32.f16.f16.f32 "
        "{%0,%1,%2,%3}, {%4,%5,%6,%7}, {%8,%9}, {%0,%1,%2,%3};"
        : "+f"(d[0]), "+f"(d[1]), "+f"(d[2]), "+f"(d[3])
        : "r"(a[0]), "r"(a[1]), "r"(a[2]), "r"(a[3]), "r"(b[0]), "r"(b[1]));
}
__device__ __forceinline__ void cp16(uint32_t dst, const void* src) {
    asm volatile("cp.async.cg.shared.global [%0], [%1], 16;"
        :: "r"(dst), "l"(src));
}

// ---------------------------------------------------------------------------
// 1-pass fp16 GEMM, 3-stage cp.async pipeline, 2 CTAs/SM.
// C[M,N] = A @ B, fp32 accum.  A [M][K], B [K][N] row-major, both fp16.
// Block tile 128 x TN_ x 32; warps 2 x (TN_/32), warp tile 64x32.
// Requires M%128==0, N%TN_==0, K%32==0.
// ---------------------------------------------------------------------------
extern __shared__ char dsm[];

template<int TN_>
__global__ __launch_bounds__(TN_ * 2, 2) void gemm1p_kernel(
    const __half* __restrict__ A, const __half* __restrict__ B,
    float* __restrict__ C, int M, int N, int K)
{
    constexpr int NT   = TN_ * 2;
    constexpr int SKB_ = TN_ + 8;
    constexpr uint32_t OFF_B = 10240;                  // A: 128 rows x 80B
    constexpr uint32_t STG   = 10240u + 32u * SKB_ * 2u;
    constexpr int BGRAN = 32 * (TN_ / 8);

    const int tid  = threadIdx.x;
    const int wid  = tid >> 5;
    const int lane = tid & 31;
    const int m0 = blockIdx.y * 128;
    const int n0 = blockIdx.x * TN_;

    const int wm = (wid & 1) * 64;
    const int wn = (wid >> 1) * 32;

    const uint32_t sb = smem_u32(dsm);

    float acc[4][4][4];
    #pragma unroll
    for (int i = 0; i < 4; i++)
        #pragma unroll
        for (int j = 0; j < 4; j++)
            #pragma unroll
            for (int k = 0; k < 4; k++) acc[i][j][k] = 0.0f;

    const int nk = K / 32;

    auto issue = [&](int slot, int kc) {
        const uint32_t s = sb + (uint32_t)slot * STG;
        #pragma unroll 2
        for (int i = tid; i < 512; i += NT) {          // A: 128 rows x 4 granules
            int r = i >> 2, c = i & 3;
            uint32_t off = (uint32_t)(r * 80 + c * 16);
            size_t g = (size_t)(m0 + r) * K + (size_t)kc * 32 + c * 8;
            cp16(s + off, A + g);
        }
        #pragma unroll 2
        for (int i = tid; i < BGRAN; i += NT) {        // B: 32 rows x TN_/8 granules
            int r = i / (TN_ / 8), c = i % (TN_ / 8);
            uint32_t off = (uint32_t)(r * (SKB_ * 2) + c * 16);
            size_t g = (size_t)(kc * 32 + r) * N + n0 + c * 8;
            cp16(s + OFF_B + off, B + g);
        }
    };

    issue(0, 0);
    asm volatile("cp.async.commit_group;");
    if (nk > 1) issue(1, 1);
    asm volatile("cp.async.commit_group;");

    const int lm_row = lane & 15;
    const int lm_kch = (lane >> 4) * 8;

    int slot = 0;
    for (int kt = 0; kt < nk; kt++) {
        if (kt + 2 < nk) {
            int ps = slot + 2; if (ps >= 3) ps -= 3;
            issue(ps, kt + 2);
        }
        asm volatile("cp.async.commit_group;");
        asm volatile("cp.async.wait_group 2;");
        __syncthreads();

        const uint32_t stg = sb + (uint32_t)slot * STG;

        #pragma unroll
        for (int ks = 0; ks < 2; ks++) {
            const int k0 = ks * 16;
            uint32_t ah[4][4], bb[2][4];
            #pragma unroll
            for (int mi = 0; mi < 4; mi++) {
                uint32_t off = (uint32_t)((wm + mi * 16 + lm_row) * 80
                                          + (k0 + lm_kch) * 2);
                ldsm_x4(ah[mi], stg + off);
            }
            #pragma unroll
            for (int np = 0; np < 2; np++) {
                uint32_t off = (uint32_t)((k0 + lm_row) * (SKB_ * 2)
                                          + (wn + np * 16 + lm_kch) * 2);
                ldsm_x4_t(bb[np], stg + OFF_B + off);
            }
            #pragma unroll
            for (int mi = 0; mi < 4; mi++) {
                #pragma unroll
                for (int nj = 0; nj < 4; nj++) {
                    const uint32_t* bp = &bb[nj >> 1][(nj & 1) * 2];
                    mma_fp16(acc[mi][nj], ah[mi], bp);
                }
            }
        }
        __syncthreads();
        slot++; if (slot >= 3) slot = 0;
    }

    const int er = lane >> 2;
    const int ec = (lane & 3) * 2;
    #pragma unroll
    for (int mi = 0; mi < 4; mi++) {
        #pragma unroll
        for (int nj = 0; nj < 4; nj++) {
            const int row = m0 + wm + mi * 16 + er;
            const int col = n0 + wn + nj * 8 + ec;
            float2 v01; v01.x = acc[mi][nj][0]; v01.y = acc[mi][nj][1];
            float2 v23; v23.x = acc[mi][nj][2]; v23.y = acc[mi][nj][3];
            *(float2*)&C[(size_t)row * N + col]       = v01;
            *(float2*)&C[(size_t)(row + 8) * N + col] = v23;
        }
    }
}

#define SMEM_T64 (3 * (10240 + 32 * 72 * 2))    // 44544
#define SMEM_T96 (3 * (10240 + 32 * 104 * 2))   // 50688

// ---------------------------------------------------------------------------
// RoPE in-place on qkv (q: 64 heads, k: 8 heads).
// ---------------------------------------------------------------------------
__global__ void rope_kernel(float* __restrict__ qkv, int n)
{
    int idx = blockIdx.x * blockDim.x + threadIdx.x;
    int total = n * (NHEADS + NKV) * (DHEAD / 2);
    if (idx >= total) return;

    int j   = idx & 31;
    int h   = (idx >> 5) % (NHEADS + NKV);
    int tok = idx / ((NHEADS + NKV) * 32);

    float* base;
    if (h < NHEADS)
        base = qkv + (size_t)tok * QKVW + h * DHEAD;
    else
        base = qkv + (size_t)tok * QKVW + NHEADS * DHEAD + (h - NHEADS) * DHEAD;

    float pos = (float)g_positions[tok];
    float inv_freq = powf(150000.0f, -((float)j) / 32.0f);
    float ang = pos * inv_freq;
    float s, c;
    sincosf(ang, &s, &c);

    float x1 = base[j];
    float x2 = base[j + 32];
    base[j]      = x1 * c - x2 * s;
    base[j + 32] = x2 * c + x1 * s;
}

// ---------------------------------------------------------------------------
// Sliding-window attention with sinks, 4 tokens per block.
// Grid: (n/4, NKV). Block: 256 threads, dynamic smem (~61 KB).
// Union window = 131 slots: slot u <-> token p0 - 127 + u (p0 = pos of tok0).
// Token j (0..3) uses slots [j, j+128). Probs at index u = j + w.
// Output written as single fp16.
// ---------------------------------------------------------------------------
#define UNI 131
// smem floats: kbuf 132*68=8976, qs 4*8*64=2048, sc 4*8*132=4224, dinv 32
#define ATTN_SMEM ((8976 + 2048 + 4224 + 32) * 4)   // 61120 B

__global__ __launch_bounds__(256) void attn_kernel(
    const float* __restrict__ qkv, const float* __restrict__ sinks,
    __half* __restrict__ out16, int n)
{
    float* kbuf = (float*)dsm;            // [132][68] (K, then V)
    float* qs   = kbuf + 8976;            // [4][8][64] scaled q
    float* sc   = qs + 2048;              // [4][8][132] scores -> probs
    float* dinv = sc + 4224;              // [32]

    const int tok0 = blockIdx.x * 4;
    const int kv   = blockIdx.y;
    const int tid  = threadIdx.x;
    const int lane = tid & 31;
    const int wid  = tid >> 5;

    const int p0 = g_positions[tok0];

    // load q for 4 tokens (4*512 floats), pre-scaled by 1/sqrt(64)
    for (int i = tid; i < 4 * GRP * DHEAD; i += 256) {
        int j = i >> 9, r = i & 511;
        qs[((j << 3) + (r >> 6)) * 64 + (r & 63)] =
            qkv[(size_t)(tok0 + j) * QKVW + (size_t)kv * GRP * DHEAD + r] * 0.125f;
    }

    // load K union window (131 rows x 64)
    for (int i = tid; i < UNI * (DHEAD / 4); i += 256) {
        int u  = i >> 4;
        int c4 = (i & 15) << 2;
        int t = p0 - (WIN - 1) + u;
        t = max(0, min(t, n - 1));
        float4 kd = *(const float4*)(qkv + (size_t)t * QKVW + NHEADS * DHEAD
                                     + (size_t)kv * DHEAD + c4);
        *(float4*)&kbuf[u * 68 + c4] = kd;
    }
    __syncthreads();

    // scores: thread u (< 131) computes dot(k[u], q[j][g]) for all j,g
    if (tid < UNI) {
        const int u = tid;
        float s[4][GRP];
        #pragma unroll
        for (int j = 0; j < 4; j++)
            #pragma unroll
            for (int g = 0; g < GRP; g++) s[j][g] = 0.0f;

        #pragma unroll 4
        for (int d4 = 0; d4 < DHEAD / 4; d4++) {
            float4 kd = *(const float4*)&kbuf[u * 68 + d4 * 4];
            #pragma unroll
            for (int j = 0; j < 4; j++)
                #pragma unroll
                for (int g = 0; g < GRP; g++) {
                    float4 qv = *(const float4*)&qs[((j << 3) + g) * 64 + d4 * 4];
                    s[j][g] += kd.x * qv.x + kd.y * qv.y
                             + kd.z * qv.z + kd.w * qv.w;
                }
        }

        const bool tvalid = (p0 - (WIN - 1) + u) >= 0;
        #pragma unroll
        for (int j = 0; j < 4; j++) {
            int w = u - j;
            bool inw = (w >= 0) && (w < WIN);
            #pragma unroll
            for (int g = 0; g < GRP; g++)
                sc[((j << 3) + g) * 132 + u] =
                    inw ? (tvalid ? s[j][g] : -INFINITY) : 0.0f;
        }
    }
    __syncthreads();

    // softmax: 32 (j,g) pairs, warp wid handles pairs p = 4*wid .. 4*wid+3
    #pragma unroll
    for (int pp = 0; pp < 4; pp++) {
        int p = (wid << 2) + pp;
        int j = p >> 3, g = p & 7;
        float* base = &sc[p * 132];
        float vals[4];
        #pragma unroll
        for (int i = 0; i < 4; i++)
            vals[i] = base[j + lane + i * 32];
        float m = fmaxf(fmaxf(vals[0], vals[1]), fmaxf(vals[2], vals[3]));
        #pragma unroll
        for (int off = 16; off; off >>= 1)
            m = fmaxf(m, __shfl_xor_sync(0xffffffffu, m, off));
        float snk = sinks[kv * GRP + g];
        m = fmaxf(m, snk);
        float ssum = 0.0f;
        #pragma unroll
        for (int i = 0; i < 4; i++) {
            float pv = expf(vals[i] - m);
            base[j + lane + i * 32] = pv;
            ssum += pv;
        }
        #pragma unroll
        for (int off = 16; off; off >>= 1)
            ssum += __shfl_xor_sync(0xffffffffu, ssum, off);
        if (lane == 0)
            dinv[p] = 1.0f / (ssum + expf(snk - m));
    }

    // load V union window into kbuf (reuse; scores-phase reads completed
    // before the post-scores __syncthreads)
    for (int i = tid; i < UNI * (DHEAD / 4); i += 256) {
        int u  = i >> 4;
        int c4 = (i & 15) << 2;
        int t = p0 - (WIN - 1) + u;
        t = max(0, min(t, n - 1));
        float4 vd = *(const float4*)(qkv + (size_t)t * QKVW
                                     + (NHEADS + NKV) * DHEAD
                                     + (size_t)kv * DHEAD + c4);
        *(float4*)&kbuf[u * 68 + c4] = vd;
    }
    __syncthreads();

    // PV: warp wid = head-in-group g, lane owns d-pair d2 = lane*2; 4 tokens
    {
        const int g  = wid;
        const int d2 = lane * 2;
        float a[4][2];
        #pragma unroll
        for (int j = 0; j < 4; j++) { a[j][0] = 0.f; a[j][1] = 0.f; }

        #pragma unroll 4
        for (int u = 0; u < UNI; u++) {
            float2 vd = *(const float2*)&kbuf[u * 68 + d2];
            #pragma unroll
            for (int j = 0; j < 4; j++) {
                float pv = sc[((j << 3) + g) * 132 + u];
                a[j][0] += pv * vd.x;
                a[j][1] += pv * vd.y;
            }
        }

        #pragma unroll
        for (int j = 0; j < 4; j++) {
            float di = dinv[(j << 3) + g];
            size_t o = (size_t)(tok0 + j) * AOW
                     + ((size_t)kv * GRP + g) * DHEAD + d2;
            __half2 hv = __halves2half2(__float2half(a[j][0] * di),
                                        __float2half(a[j][1] * di));
            *(__half2*)&out16[o] = hv;
        }
    }
}

// ---------------------------------------------------------------------------
extern "C" void kernel_launch(void* const* d_in, const int* in_sizes, int n_in,
                              void* d_out, int out_size)
{
    const float* hs    = (const float*)d_in[0];
    const float* wqkv  = (const float*)d_in[1];
    const float* wo    = (const float*)d_in[2];
    const float* sinks = (const float*)d_in[3];
    const void*  pos   = (const void*)d_in[4];
    float*       out   = (float*)d_out;

    const int n = in_sizes[0] / HDIM;   // 1024

    float* qkv_ptr;
    __half *ah, *ath, *wq, *wo16;
    cudaGetSymbolAddress((void**)&qkv_ptr, g_qkv);
    cudaGetSymbolAddress((void**)&ah,   g_ah);
    cudaGetSymbolAddress((void**)&ath,  g_ath);
    cudaGetSymbolAddress((void**)&wq,   g_wq);
    cudaGetSymbolAddress((void**)&wo16, g_wo);

    cudaFuncSetAttribute(gemm1p_kernel<64>,
                         cudaFuncAttributeMaxDynamicSharedMemorySize, SMEM_T64);
    cudaFuncSetAttribute(gemm1p_kernel<96>,
                         cudaFuncAttributeMaxDynamicSharedMemorySize, SMEM_T96);
    cudaFuncSetAttribute(attn_kernel,
                         cudaFuncAttributeMaxDynamicSharedMemorySize, ATTN_SMEM);

    // 0) normalize positions
    norm_pos_kernel<<<1, 1024>>>(pos, n);

    // 1) fp16 conversions: hs, Wqkv, Wo
    {
        int n4 = (n * HDIM) / 4;
        cvt_h_kernel<<<(n4 + 255) / 256, 256>>>(hs, ah, n4);
        n4 = (HDIM * QKVW) / 4;
        cvt_h_kernel<<<(n4 + 255) / 256, 256>>>(wqkv, wq, n4);
        n4 = (AOW * HDIM) / 4;
        cvt_h_kernel<<<(n4 + 255) / 256, 256>>>(wo, wo16, n4);
    }

    // 2) qkv = hs @ Wqkv   (fp16 1-pass, N tile 64: 5120 = 80*64)
    {
        dim3 grid(QKVW / 64, n / 128);
        gemm1p_kernel<64><<<grid, 128, SMEM_T64>>>(ah, wq, qkv_ptr,
                                                   n, QKVW, HDIM);
    }

    // 3) RoPE in place on q and k
    {
        int total = n * (NHEADS + NKV) * (DHEAD / 2);
        rope_kernel<<<(total + 255) / 256, 256>>>(qkv_ptr, n);
    }

    // 4) attention (4 tokens/block), writes fp16 directly
    {
        dim3 grid(n / 4, NKV);
        attn_kernel<<<grid, 256, ATTN_SMEM>>>(qkv_ptr, sinks, ath, n);
    }

    // 5) out = attn @ Wo   (fp16 1-pass, N tile 96: 2880 = 30*96, single wave)
    {
        dim3 grid(HDIM / 96, n / 128);
        gemm1p_kernel<96><<<grid, 192, SMEM_T96>>>(ath, wo16, out,
                                                   n, HDIM, AOW);
    }
}